// round 1
// baseline (speedup 1.0000x reference)
#include <cuda_runtime.h>

#define BATCH  64
#define NPG    512
#define NTOT   32768
#define EDGES  524288
#define EPG    8192
#define ODIM   200
#define IDIM   100
#define H3     600
#define CDIM   300
#define L1     510
#define P1     254
#define P2     127
#define GP1    16256   /* 64*254 */
#define GP2    8128    /* 64*127 */
#define NCLS   7

// ----------------------------- device scratch -----------------------------
__device__ float d_h0[NTOT*ODIM];
__device__ float d_h1[NTOT*ODIM];
__device__ float d_Amat[NTOT*4*ODIM];
__device__ float d_amsg[NTOT*ODIM];
__device__ float d_gi[NTOT*H3];
__device__ float d_gh[NTOT*H3];
__device__ float d_Wstack[4*ODIM*ODIM];
__device__ float d_WihT[ODIM*H3];
__device__ float d_WhhT[ODIM*H3];
__device__ float d_nbias[NTOT*ODIM];
__device__ int   d_deg4[NTOT*4];
__device__ int   d_indptr[NTOT+1];
__device__ int   d_srcs[EDGES];
__device__ int   d_typs[EDGES];
__device__ float d_cT[CDIM*NTOT + 64];
__device__ float d_w1y[3*ODIM*ODIM];
__device__ float d_w1z[3*CDIM*CDIM];
__device__ float d_y1[ODIM*NTOT];
__device__ float d_z1[CDIM*NTOT];
__device__ float d_yp1[ODIM*GP1];
__device__ float d_zp1[CDIM*GP1];
__device__ float d_y2[ODIM*GP1];
__device__ float d_z2[CDIM*GP1];
__device__ float d_yp2[ODIM*GP2];
__device__ float d_zp2[CDIM*GP2];
__device__ float d_ly[NCLS*GP2];
__device__ float d_lz[NCLS*GP2];

// ----------------------------- small kernels ------------------------------
__global__ void zero_int_k(int* p, int n) {
    int i = blockIdx.x * blockDim.x + threadIdx.x;
    if (i < n) p[i] = 0;
}

__global__ void hist_k(const int* __restrict__ edst, const int* __restrict__ etyp) {
    int e = blockIdx.x * blockDim.x + threadIdx.x;
    if (e < EDGES) atomicAdd(&d_deg4[edst[e] * 4 + etyp[e]], 1);
}

// exclusive scan of per-node degrees (sum of 4 type counts) -> indptr
__global__ void scan_k() {
    __shared__ int ssum[1024];
    int t = threadIdx.x;
    int loc[32];
    int s = 0;
#pragma unroll
    for (int i = 0; i < 32; i++) {
        int n = t * 32 + i;
        int d = d_deg4[n*4] + d_deg4[n*4+1] + d_deg4[n*4+2] + d_deg4[n*4+3];
        loc[i] = s; s += d;
    }
    ssum[t] = s;
    __syncthreads();
    if (t == 0) {
        int acc = 0;
        for (int i = 0; i < 1024; i++) { int v = ssum[i]; ssum[i] = acc; acc += v; }
        d_indptr[NTOT] = acc;
    }
    __syncthreads();
    int off = ssum[t];
#pragma unroll
    for (int i = 0; i < 32; i++) d_indptr[t * 32 + i] = off + loc[i];
}

// Deterministic CSR build: one block per graph, one thread per local node.
// Stable (edge-index order) -> bitwise deterministic SPMM later.
__global__ void build_csr_k(const int* __restrict__ esrc, const int* __restrict__ edst,
                            const int* __restrict__ etyp) {
    __shared__ int sd[512], ss[512], st[512];
    int b = blockIdx.x;
    int node = b * NPG + threadIdx.x;
    int pos = d_indptr[node];
    int base = b * EPG;
    for (int c = 0; c < EPG; c += 512) {
        sd[threadIdx.x] = edst[base + c + threadIdx.x];
        ss[threadIdx.x] = esrc[base + c + threadIdx.x];
        st[threadIdx.x] = etyp[base + c + threadIdx.x];
        __syncthreads();
        for (int i = 0; i < 512; i++) {
            if (sd[i] == node) { d_srcs[pos] = ss[i]; d_typs[pos] = st[i]; pos++; }
        }
        __syncthreads();
    }
}

// etype_W [4][o][d] -> Wstack[(t*200+d)][o]
__global__ void pack_wstack_k(const float* __restrict__ W) {
    int idx = blockIdx.x * blockDim.x + threadIdx.x;
    if (idx < 4 * ODIM * ODIM) {
        int o = idx % ODIM;
        int d = (idx / ODIM) % ODIM;
        int t = idx / (ODIM * ODIM);
        d_Wstack[(t * ODIM + d) * ODIM + o] = W[(t * ODIM + o) * ODIM + d];
    }
}

// W[600][200] -> out[200][600]
__global__ void pack_T_k(const float* __restrict__ W, float* __restrict__ out) {
    int idx = blockIdx.x * blockDim.x + threadIdx.x;
    if (idx < ODIM * H3) {
        int j = idx % H3;
        int d = idx / H3;
        out[d * H3 + j] = W[j * ODIM + d];
    }
}

// conv weight [C][C][3] -> [k][co][ci]
__global__ void pack_conv_k(const float* __restrict__ W, float* __restrict__ out, int C) {
    int idx = blockIdx.x * blockDim.x + threadIdx.x;
    if (idx < 3 * C * C) {
        int ci = idx % C;
        int co = (idx / C) % C;
        int k  = idx / (C * C);
        out[idx] = W[(co * C + ci) * 3 + k];
    }
}

__global__ void init_h_k(const float* __restrict__ feat) {
    int idx = blockIdx.x * blockDim.x + threadIdx.x;
    if (idx < NTOT * ODIM) {
        int d = idx % ODIM;
        int n = idx / ODIM;
        d_h0[idx] = (d < IDIM) ? feat[n * IDIM + d] : 0.f;
    }
}

// nbias[n][o] = sum_t deg4[n][t] * etype_b[t][o]
__global__ void nodebias_k(const float* __restrict__ eb) {
    int idx = blockIdx.x * blockDim.x + threadIdx.x;
    if (idx < NTOT * ODIM) {
        int o = idx % ODIM;
        int n = idx / ODIM;
        float s = 0.f;
#pragma unroll
        for (int t = 0; t < 4; t++) s += (float)d_deg4[n * 4 + t] * eb[t * ODIM + o];
        d_nbias[idx] = s;
    }
}

// A_cat[n][t*200+d] = sum over CSR edges of node n with type t of h[src][d]
__global__ void spmm_k(const float* __restrict__ h) {
    __shared__ int ss[128], st[128];
    int n = blockIdx.x;
    int tid = threadIdx.x;
    int beg = d_indptr[n], end = d_indptr[n + 1];
    float a0 = 0.f, a1 = 0.f, a2 = 0.f, a3 = 0.f;
    for (int base = beg; base < end; base += 128) {
        int cnt = min(128, end - base);
        if (tid < cnt) { ss[tid] = d_srcs[base + tid]; st[tid] = d_typs[base + tid]; }
        __syncthreads();
        if (tid < ODIM) {
            for (int e = 0; e < cnt; e++) {
                float v = h[ss[e] * ODIM + tid];
                int t = st[e];
                a0 += (t == 0) ? v : 0.f;
                a1 += (t == 1) ? v : 0.f;
                a2 += (t == 2) ? v : 0.f;
                a3 += (t == 3) ? v : 0.f;
            }
        }
        __syncthreads();
    }
    if (tid < ODIM) {
        float* Ar = &d_Amat[(size_t)n * 800];
        Ar[tid]       = a0;
        Ar[200 + tid] = a1;
        Ar[400 + tid] = a2;
        Ar[600 + tid] = a3;
    }
}

// ------------------------------- GEMM -------------------------------------
// C[M,N] = A[M,K] * B[K,N] (+bias)(+C).  Row-major, arbitrary ld.
// BMODE: 0 none, 1 bias[col], 2 bias matrix [M,N], 3 bias[row]
template<int BMODE, bool ACC>
__global__ __launch_bounds__(256) void gemm_k(
    const float* __restrict__ A, const float* __restrict__ B,
    float* __restrict__ C, const float* __restrict__ bias,
    int M, int N, int K, int lda, int ldb, int ldc)
{
    __shared__ float As[16][68];
    __shared__ float Bs[16][68];
    const int tid = threadIdx.x;
    const int tx = tid & 15;
    const int ty = tid >> 4;
    const int row0 = blockIdx.y * 64;
    const int col0 = blockIdx.x * 64;
    float acc[4][4] = {};
    const int numK = (K + 15) >> 4;
    for (int kt = 0; kt < numK; kt++) {
        int k0 = kt << 4;
#pragma unroll
        for (int i = 0; i < 4; i++) {          // A tile 64x16
            int e = tid + (i << 8);
            int r = e >> 4, c = e & 15;
            int gr = row0 + r, gk = k0 + c;
            As[c][r] = (gr < M && gk < K) ? A[(size_t)gr * lda + gk] : 0.f;
        }
#pragma unroll
        for (int i = 0; i < 4; i++) {          // B tile 16x64
            int e = tid + (i << 8);
            int r = e >> 6, c = e & 63;
            int gk = k0 + r, gc = col0 + c;
            Bs[r][c] = (gk < K && gc < N) ? B[(size_t)gk * ldb + gc] : 0.f;
        }
        __syncthreads();
#pragma unroll
        for (int kk = 0; kk < 16; kk++) {
            float4 a4 = *(const float4*)&As[kk][ty * 4];
            float4 b4 = *(const float4*)&Bs[kk][tx * 4];
            float av[4] = {a4.x, a4.y, a4.z, a4.w};
            float bv[4] = {b4.x, b4.y, b4.z, b4.w};
#pragma unroll
            for (int i = 0; i < 4; i++)
#pragma unroll
                for (int j = 0; j < 4; j++) acc[i][j] += av[i] * bv[j];
        }
        __syncthreads();
    }
#pragma unroll
    for (int i = 0; i < 4; i++) {
        int r = row0 + ty * 4 + i;
        if (r >= M) continue;
#pragma unroll
        for (int j = 0; j < 4; j++) {
            int c = col0 + tx * 4 + j;
            if (c >= N) continue;
            float v = acc[i][j];
            if (BMODE == 1) v += bias[c];
            else if (BMODE == 2) v += bias[(size_t)r * N + c];
            else if (BMODE == 3) v += bias[r];
            size_t o = (size_t)r * ldc + c;
            if (ACC) v += C[o];
            C[o] = v;
        }
    }
}

static void run_gemm(const float* A, const float* B, float* C, const float* bias,
                     int M, int N, int K, int lda, int ldb, int ldc,
                     int bmode, bool acc)
{
    dim3 grid((N + 63) / 64, (M + 63) / 64);
    if (acc) { gemm_k<0, true><<<grid, 256>>>(A, B, C, bias, M, N, K, lda, ldb, ldc); return; }
    switch (bmode) {
        case 0: gemm_k<0, false><<<grid, 256>>>(A, B, C, bias, M, N, K, lda, ldb, ldc); break;
        case 1: gemm_k<1, false><<<grid, 256>>>(A, B, C, bias, M, N, K, lda, ldb, ldc); break;
        case 2: gemm_k<2, false><<<grid, 256>>>(A, B, C, bias, M, N, K, lda, ldb, ldc); break;
        case 3: gemm_k<3, false><<<grid, 256>>>(A, B, C, bias, M, N, K, lda, ldb, ldc); break;
    }
}

// GRU gates
__global__ void gates_k(const float* __restrict__ hin, float* __restrict__ hout) {
    int idx = blockIdx.x * blockDim.x + threadIdx.x;
    if (idx < NTOT * ODIM) {
        int n = idx / ODIM;
        int o = idx % ODIM;
        size_t b6 = (size_t)n * H3;
        float ir  = d_gi[b6 + o],        hr = d_gh[b6 + o];
        float iz  = d_gi[b6 + 200 + o],  hz = d_gh[b6 + 200 + o];
        float inn = d_gi[b6 + 400 + o],  hn = d_gh[b6 + 400 + o];
        float r = 1.f / (1.f + __expf(-(ir + hr)));
        float z = 1.f / (1.f + __expf(-(iz + hz)));
        float nn = tanhf(inn + r * hn);
        hout[idx] = (1.f - z) * nn + z * hin[idx];
    }
}

// in [G][C] -> out [C][G]
__global__ void transpose_k(const float* __restrict__ in, float* __restrict__ out,
                            int G, int C) {
    __shared__ float tile[32][33];
    int c0 = blockIdx.x * 32;
    int g0 = blockIdx.y * 32;
    int c = c0 + threadIdx.x;
#pragma unroll
    for (int j = 0; j < 32; j += 8) {
        int g = g0 + threadIdx.y + j;
        tile[threadIdx.y + j][threadIdx.x] = (c < C && g < G) ? in[(size_t)g * C + c] : 0.f;
    }
    __syncthreads();
    int g = g0 + threadIdx.x;
#pragma unroll
    for (int j = 0; j < 32; j += 8) {
        int cc = c0 + threadIdx.y + j;
        if (cc < C && g < G) out[(size_t)cc * G + g] = tile[threadIdx.x][threadIdx.y + j];
    }
}

// relu+maxpool k3 s2: [C][32768 (b,l<510 valid)] -> [C][64*254]
__global__ void pool3_k(const float* __restrict__ in, float* __restrict__ out, int C) {
    int idx = blockIdx.x * blockDim.x + threadIdx.x;
    if (idx < C * GP1) {
        int co = idx / GP1;
        int r = idx % GP1;
        int b = r / P1, p = r % P1;
        int base = co * NTOT + b * NPG + 2 * p;
        float m = fmaxf(fmaxf(in[base], in[base + 1]), in[base + 2]);
        out[idx] = fmaxf(m, 0.f);
    }
}

// relu+maxpool k2 s2: [C][64*254] -> [C][64*127]
__global__ void pool2_k(const float* __restrict__ in, float* __restrict__ out, int C) {
    int idx = blockIdx.x * blockDim.x + threadIdx.x;
    if (idx < C * GP2) {
        int co = idx / GP2;
        int r = idx % GP2;
        int b = r / P2, p = r % P2;
        int base = co * GP1 + b * P1 + 2 * p;
        out[idx] = fmaxf(fmaxf(in[base], in[base + 1]), 0.f);
    }
}

// (ly + by) * (lz + bz), mean over 127, softmax over 7
__global__ void final_k(const float* __restrict__ by, const float* __restrict__ bz,
                        float* __restrict__ out) {
    __shared__ float red[NCLS][128];
    int b = blockIdx.x;
    int tid = threadIdx.x;
    float part[NCLS] = {};
    for (int p = tid; p < P2; p += blockDim.x) {
        int base = b * P2 + p;
#pragma unroll
        for (int cl = 0; cl < NCLS; cl++) {
            float y = d_ly[cl * GP2 + base] + by[cl];
            float z = d_lz[cl * GP2 + base] + bz[cl];
            part[cl] += y * z;
        }
    }
#pragma unroll
    for (int cl = 0; cl < NCLS; cl++) red[cl][tid] = part[cl];
    __syncthreads();
    if (tid == 0) {
        float v[NCLS];
        for (int cl = 0; cl < NCLS; cl++) {
            float s = 0.f;
            for (int i = 0; i < 128; i++) s += red[cl][i];
            v[cl] = s / (float)P2;
        }
        float mx = v[0];
        for (int cl = 1; cl < NCLS; cl++) mx = fmaxf(mx, v[cl]);
        float se = 0.f;
        for (int cl = 0; cl < NCLS; cl++) { v[cl] = __expf(v[cl] - mx); se += v[cl]; }
        for (int cl = 0; cl < NCLS; cl++) out[b * NCLS + cl] = v[cl] / se;
    }
}

// ----------------------------- host side ----------------------------------
static void* getsym(const void* s) {
    void* p = nullptr;
    cudaGetSymbolAddress(&p, s);
    return p;
}

extern "C" void kernel_launch(void* const* d_in, const int* in_sizes, int n_in,
                              void* d_out, int out_size)
{
    const float* features = (const float*)d_in[0];
    const int*   esrc     = (const int*)  d_in[1];
    const int*   edst     = (const int*)  d_in[2];
    const int*   etyp     = (const int*)  d_in[3];
    const float* etype_W  = (const float*)d_in[4];
    const float* etype_b  = (const float*)d_in[5];
    const float* W_ih     = (const float*)d_in[6];
    const float* b_ih     = (const float*)d_in[7];
    const float* W_hh     = (const float*)d_in[8];
    const float* b_hh     = (const float*)d_in[9];
    const float* conv1_w  = (const float*)d_in[10];
    const float* conv1_b  = (const float*)d_in[11];
    const float* conv2_w  = (const float*)d_in[12];
    const float* conv2_b  = (const float*)d_in[13];
    const float* convc1_w = (const float*)d_in[14];
    const float* convc1_b = (const float*)d_in[15];
    const float* convc2_w = (const float*)d_in[16];
    const float* convc2_b = (const float*)d_in[17];
    const float* mlp_y_w  = (const float*)d_in[18];
    const float* mlp_y_b  = (const float*)d_in[19];
    const float* mlp_z_w  = (const float*)d_in[20];
    const float* mlp_z_b  = (const float*)d_in[21];

    float* p_h0    = (float*)getsym(d_h0);
    float* p_h1    = (float*)getsym(d_h1);
    float* p_Amat  = (float*)getsym(d_Amat);
    float* p_amsg  = (float*)getsym(d_amsg);
    float* p_gi    = (float*)getsym(d_gi);
    float* p_gh    = (float*)getsym(d_gh);
    float* p_Wst   = (float*)getsym(d_Wstack);
    float* p_WihT  = (float*)getsym(d_WihT);
    float* p_WhhT  = (float*)getsym(d_WhhT);
    float* p_nb    = (float*)getsym(d_nbias);
    int*   p_deg4  = (int*)  getsym(d_deg4);
    float* p_cT    = (float*)getsym(d_cT);
    float* p_w1y   = (float*)getsym(d_w1y);
    float* p_w1z   = (float*)getsym(d_w1z);
    float* p_y1    = (float*)getsym(d_y1);
    float* p_z1    = (float*)getsym(d_z1);
    float* p_yp1   = (float*)getsym(d_yp1);
    float* p_zp1   = (float*)getsym(d_zp1);
    float* p_y2    = (float*)getsym(d_y2);
    float* p_z2    = (float*)getsym(d_z2);
    float* p_yp2   = (float*)getsym(d_yp2);
    float* p_zp2   = (float*)getsym(d_zp2);
    float* p_ly    = (float*)getsym(d_ly);
    float* p_lz    = (float*)getsym(d_lz);

    const int T = 256;

    // ---- setup: CSR (deterministic) + weight packing + init ----
    zero_int_k<<<(NTOT * 4 + T - 1) / T, T>>>(p_deg4, NTOT * 4);
    hist_k<<<(EDGES + T - 1) / T, T>>>(edst, etyp);
    scan_k<<<1, 1024>>>();
    build_csr_k<<<BATCH, 512>>>(esrc, edst, etyp);
    pack_wstack_k<<<(4 * ODIM * ODIM + T - 1) / T, T>>>(etype_W);
    pack_T_k<<<(ODIM * H3 + T - 1) / T, T>>>(W_ih, p_WihT);
    pack_T_k<<<(ODIM * H3 + T - 1) / T, T>>>(W_hh, p_WhhT);
    pack_conv_k<<<(3 * ODIM * ODIM + T - 1) / T, T>>>(conv1_w, p_w1y, ODIM);
    pack_conv_k<<<(3 * CDIM * CDIM + T - 1) / T, T>>>(convc1_w, p_w1z, CDIM);
    init_h_k<<<(NTOT * ODIM + T - 1) / T, T>>>(features);
    nodebias_k<<<(NTOT * ODIM + T - 1) / T, T>>>(etype_b);

    // ---- GGNN: 8 steps ----
    const int NE = NTOT * ODIM;
    for (int s = 0; s < 8; s++) {
        const float* hin = (s & 1) ? p_h1 : p_h0;
        float*       hout = (s & 1) ? p_h0 : p_h1;
        spmm_k<<<NTOT, 256>>>(hin);
        // a = A_cat @ Wstack + nodebias
        run_gemm(p_Amat, p_Wst, p_amsg, p_nb, NTOT, ODIM, 800, 800, ODIM, ODIM, 2, false);
        // gi = a @ Wih^T + b_ih ; gh = h @ Whh^T + b_hh
        run_gemm(p_amsg, p_WihT, p_gi, b_ih, NTOT, H3, ODIM, ODIM, H3, H3, 1, false);
        run_gemm(hin,    p_WhhT, p_gh, b_hh, NTOT, H3, ODIM, ODIM, H3, H3, 1, false);
        gates_k<<<(NE + T - 1) / T, T>>>(hin, hout);
    }
    float* p_hf = p_h0;  // after 8 steps result is in h0

    // ---- readout ----
    // cT[0:200][g] = h, cT[200:300][g] = features
    transpose_k<<<dim3((ODIM + 31) / 32, NTOT / 32), dim3(32, 8)>>>(p_hf, p_cT, NTOT, ODIM);
    transpose_k<<<dim3((IDIM + 31) / 32, NTOT / 32), dim3(32, 8)>>>(features, p_cT + (size_t)ODIM * NTOT, NTOT, IDIM);

    // Y branch: conv k=3 as 3 accumulating GEMMs over shifted cT
    for (int k = 0; k < 3; k++)
        run_gemm(p_w1y + k * ODIM * ODIM, p_cT + k, p_y1, conv1_b,
                 ODIM, NTOT, ODIM, ODIM, NTOT, NTOT, (k == 0) ? 3 : 0, k > 0);
    pool3_k<<<(ODIM * GP1 + T - 1) / T, T>>>(p_y1, p_yp1, ODIM);
    run_gemm(conv2_w, p_yp1, p_y2, conv2_b, ODIM, GP1, ODIM, ODIM, GP1, GP1, 3, false);
    pool2_k<<<(ODIM * GP2 + T - 1) / T, T>>>(p_y2, p_yp2, ODIM);

    // Z branch (concat input, C=300)
    for (int k = 0; k < 3; k++)
        run_gemm(p_w1z + k * CDIM * CDIM, p_cT + k, p_z1, convc1_b,
                 CDIM, NTOT, CDIM, CDIM, NTOT, NTOT, (k == 0) ? 3 : 0, k > 0);
    pool3_k<<<(CDIM * GP1 + T - 1) / T, T>>>(p_z1, p_zp1, CDIM);
    run_gemm(convc2_w, p_zp1, p_z2, convc2_b, CDIM, GP1, CDIM, CDIM, GP1, GP1, 3, false);
    pool2_k<<<(CDIM * GP2 + T - 1) / T, T>>>(p_z2, p_zp2, CDIM);

    // gating MLPs (bias added in final kernel)
    run_gemm(mlp_y_w, p_yp2, p_ly, nullptr, NCLS, GP2, ODIM, ODIM, GP2, GP2, 0, false);
    run_gemm(mlp_z_w, p_zp2, p_lz, nullptr, NCLS, GP2, CDIM, CDIM, GP2, GP2, 0, false);

    final_k<<<BATCH, 128>>>(mlp_y_b, mlp_z_b, (float*)d_out);
}

// round 2
// speedup vs baseline: 1.0621x; 1.0621x over previous
#include <cuda_runtime.h>

#define BATCH  64
#define NPG    512
#define NTOT   32768
#define EDGES  524288
#define EPG    8192
#define NCHK   16      /* 8192/512 chunks per graph */
#define ODIM   200
#define IDIM   100
#define H3     600
#define CDIM   300
#define P1     254
#define P2     127
#define GP1    16256   /* 64*254 */
#define GP2    8128    /* 64*127 */
#define NCLS   7

// ----------------------------- device scratch -----------------------------
__device__ float d_h0[NTOT*ODIM];
__device__ float d_h1[NTOT*ODIM];
__device__ float d_Amat[NTOT*4*ODIM];
__device__ float d_amsg[NTOT*ODIM];
__device__ float d_gi[NTOT*H3];
__device__ float d_gh[NTOT*H3];
__device__ float d_Wstack[4*ODIM*ODIM];
__device__ float d_WihT[ODIM*H3];
__device__ float d_WhhT[ODIM*H3];
__device__ float d_nbias[NTOT*ODIM];
__device__ int   d_deg4[NTOT*4];
__device__ int   d_indptr[NTOT+1];
__device__ int   d_ccnt[NTOT*NCHK];
__device__ int   d_srcs[EDGES];
__device__ int   d_typs[EDGES];
__device__ float d_cT[CDIM*NTOT + 64];
__device__ float d_w1y[3*ODIM*ODIM];
__device__ float d_w1z[3*CDIM*CDIM];
__device__ float d_y1[ODIM*NTOT];
__device__ float d_z1[CDIM*NTOT];
__device__ float d_yp1[ODIM*GP1];
__device__ float d_zp1[CDIM*GP1];
__device__ float d_y2[ODIM*GP1];
__device__ float d_z2[CDIM*GP1];
__device__ float d_yp2[ODIM*GP2];
__device__ float d_zp2[CDIM*GP2];
__device__ float d_ly[NCLS*GP2];
__device__ float d_lz[NCLS*GP2];

// ----------------------------- setup kernels ------------------------------
__global__ void zero_int_k(int* p, int n) {
    int i = blockIdx.x * blockDim.x + threadIdx.x;
    if (i < n) p[i] = 0;
}

__global__ void hist_k(const int* __restrict__ edst, const int* __restrict__ etyp) {
    int e = blockIdx.x * blockDim.x + threadIdx.x;
    if (e < EDGES) atomicAdd(&d_deg4[edst[e] * 4 + etyp[e]], 1);
}

// exclusive scan of per-node degrees -> indptr
__global__ void scan_k() {
    __shared__ int ssum[1024];
    int t = threadIdx.x;
    int loc[32];
    int s = 0;
#pragma unroll
    for (int i = 0; i < 32; i++) {
        int n = t * 32 + i;
        int d = d_deg4[n*4] + d_deg4[n*4+1] + d_deg4[n*4+2] + d_deg4[n*4+3];
        loc[i] = s; s += d;
    }
    ssum[t] = s;
    __syncthreads();
    if (t == 0) {
        int acc = 0;
        for (int i = 0; i < 1024; i++) { int v = ssum[i]; ssum[i] = acc; acc += v; }
        d_indptr[NTOT] = acc;
    }
    __syncthreads();
    int off = ssum[t];
#pragma unroll
    for (int i = 0; i < 32; i++) d_indptr[t * 32 + i] = off + loc[i];
}

// per-(graph,chunk) histogram over local dst
__global__ void chunk_hist_k(const int* __restrict__ edst) {
    __shared__ int h[NPG];
    int g = blockIdx.y, c = blockIdx.x;
    h[threadIdx.x] = 0;
    __syncthreads();
    int e = g * EPG + c * 512 + threadIdx.x;
    atomicAdd(&h[edst[e] - g * NPG], 1);
    __syncthreads();
    d_ccnt[(g * NPG + threadIdx.x) * NCHK + c] = h[threadIdx.x];
}

// per-node scan across chunks: ccnt[n][c] -> global write base for chunk c
__global__ void chunk_scan_k() {
    int n = blockIdx.x * blockDim.x + threadIdx.x;
    if (n < NTOT) {
        int base = d_indptr[n];
#pragma unroll
        for (int c = 0; c < NCHK; c++) {
            int v = d_ccnt[n * NCHK + c];
            d_ccnt[n * NCHK + c] = base;
            base += v;
        }
    }
}

// stable scatter: rank within chunk by edge index
__global__ void scatter_k(const int* __restrict__ esrc, const int* __restrict__ edst,
                          const int* __restrict__ etyp) {
    __shared__ int sd[512];
    int g = blockIdx.y, c = blockIdx.x;
    int e = g * EPG + c * 512 + threadIdx.x;
    int dl = edst[e] - g * NPG;
    sd[threadIdx.x] = dl;
    __syncthreads();
    int rank = 0;
    for (int i = 0; i < threadIdx.x; i++) rank += (sd[i] == dl);
    int pos = d_ccnt[(g * NPG + dl) * NCHK + c] + rank;
    d_srcs[pos] = esrc[e];
    d_typs[pos] = etyp[e];
}

// etype_W [4][o][d] -> Wstack[(t*200+d)][o]
__global__ void pack_wstack_k(const float* __restrict__ W) {
    int idx = blockIdx.x * blockDim.x + threadIdx.x;
    if (idx < 4 * ODIM * ODIM) {
        int o = idx % ODIM;
        int d = (idx / ODIM) % ODIM;
        int t = idx / (ODIM * ODIM);
        d_Wstack[(t * ODIM + d) * ODIM + o] = W[(t * ODIM + o) * ODIM + d];
    }
}

// W[600][200] -> out[200][600]
__global__ void pack_T_k(const float* __restrict__ W, float* __restrict__ out) {
    int idx = blockIdx.x * blockDim.x + threadIdx.x;
    if (idx < ODIM * H3) {
        int j = idx % H3;
        int d = idx / H3;
        out[d * H3 + j] = W[j * ODIM + d];
    }
}

// conv weight [C][C][3] -> [k][co][ci]
__global__ void pack_conv_k(const float* __restrict__ W, float* __restrict__ out, int C) {
    int idx = blockIdx.x * blockDim.x + threadIdx.x;
    if (idx < 3 * C * C) {
        int ci = idx % C;
        int co = (idx / C) % C;
        int k  = idx / (C * C);
        out[idx] = W[(co * C + ci) * 3 + k];
    }
}

__global__ void init_h_k(const float* __restrict__ feat) {
    int idx = blockIdx.x * blockDim.x + threadIdx.x;
    if (idx < NTOT * ODIM) {
        int d = idx % ODIM;
        int n = idx / ODIM;
        d_h0[idx] = (d < IDIM) ? feat[n * IDIM + d] : 0.f;
    }
}

// nbias[n][o] = sum_t deg4[n][t] * etype_b[t][o]
__global__ void nodebias_k(const float* __restrict__ eb) {
    int idx = blockIdx.x * blockDim.x + threadIdx.x;
    if (idx < NTOT * ODIM) {
        int o = idx % ODIM;
        int n = idx / ODIM;
        float s = 0.f;
#pragma unroll
        for (int t = 0; t < 4; t++) s += (float)d_deg4[n * 4 + t] * eb[t * ODIM + o];
        d_nbias[idx] = s;
    }
}

// A_cat[n][t*200+d] = sum over CSR edges of node n with type t of h[src][d]
__global__ void spmm_k(const float* __restrict__ h) {
    __shared__ int ss[128], st[128];
    int n = blockIdx.x;
    int tid = threadIdx.x;
    int beg = d_indptr[n], end = d_indptr[n + 1];
    float a0 = 0.f, a1 = 0.f, a2 = 0.f, a3 = 0.f;
    for (int base = beg; base < end; base += 128) {
        int cnt = min(128, end - base);
        if (tid < cnt) { ss[tid] = d_srcs[base + tid]; st[tid] = d_typs[base + tid]; }
        __syncthreads();
        if (tid < ODIM) {
            for (int e = 0; e < cnt; e++) {
                float v = h[ss[e] * ODIM + tid];
                int t = st[e];
                a0 += (t == 0) ? v : 0.f;
                a1 += (t == 1) ? v : 0.f;
                a2 += (t == 2) ? v : 0.f;
                a3 += (t == 3) ? v : 0.f;
            }
        }
        __syncthreads();
    }
    if (tid < ODIM) {
        float* Ar = &d_Amat[(size_t)n * 800];
        Ar[tid]       = a0;
        Ar[200 + tid] = a1;
        Ar[400 + tid] = a2;
        Ar[600 + tid] = a3;
    }
}

// ------------------------------- GEMM -------------------------------------
// C[M,N] = sum_s A_s[M,K] * B_s[K,N] (+bias).  A_s = A + s*aStep, B_s = B + s
// (column shift; caller guarantees B has >= NSPLIT-1 floats of padding).
// Requires: K%4==0, lda%4==0, ldb%4==0, ldc%4==0, 16B-aligned A/B/C.
// BMODE: 0 none, 1 bias[col], 2 bias matrix [M,N], 3 bias[row]
template<int BMODE, int NSPLIT>
__global__ __launch_bounds__(256) void gemm_k(
    const float* __restrict__ A, const float* __restrict__ B,
    float* __restrict__ C, const float* __restrict__ bias,
    int M, int N, int K, int lda, int ldb, int ldc, int aStep)
{
    __shared__ float As[2][8][128];
    __shared__ float Bs[2][8][128];
    const int tid = threadIdx.x;
    const int tx = tid & 15;
    const int ty = tid >> 4;
    const int row0 = blockIdx.y * 128;
    const int col0 = blockIdx.x * 128;

    const int ktiles = (K + 7) >> 3;
    const int total = ktiles * NSPLIT;

    const int ar = tid >> 1;             // A row within tile (0..127)
    const int ac = (tid & 1) << 2;       // A k-offset (0 or 4)
    const int arow = row0 + ar;

    float4 pa;
    float pb[4];

    // ---- load tile 0 ----
    {
        pa = make_float4(0.f, 0.f, 0.f, 0.f);
        if (arow < M && ac < K)
            pa = *(const float4*)(A + (size_t)arow * lda + ac);
#pragma unroll
        for (int i = 0; i < 4; i++) {
            int idx = tid + (i << 8);
            int kr = idx >> 7, cc = idx & 127;
            int cg = col0 + cc;
            pb[i] = (kr < K && cg < N) ? B[(size_t)kr * ldb + cg] : 0.f;
        }
        As[0][ac + 0][ar] = pa.x;
        As[0][ac + 1][ar] = pa.y;
        As[0][ac + 2][ar] = pa.z;
        As[0][ac + 3][ar] = pa.w;
#pragma unroll
        for (int i = 0; i < 4; i++) {
            int idx = tid + (i << 8);
            Bs[0][idx >> 7][idx & 127] = pb[i];
        }
    }
    __syncthreads();

    float acc[8][8] = {};
    int buf = 0;

    for (int t = 0; t < total; t++) {
        int tn = t + 1;
        if (tn < total) {
            int s  = (NSPLIT == 1) ? 0  : (tn / ktiles);
            int kt = (NSPLIT == 1) ? tn : (tn % ktiles);
            int k0 = kt << 3;
            const float* Ap = A + (size_t)s * aStep;
            pa = make_float4(0.f, 0.f, 0.f, 0.f);
            int ka = k0 + ac;
            if (arow < M && ka < K)
                pa = *(const float4*)(Ap + (size_t)arow * lda + ka);
#pragma unroll
            for (int i = 0; i < 4; i++) {
                int idx = tid + (i << 8);
                int kr = k0 + (idx >> 7), cc = idx & 127;
                int cg = col0 + cc;
                pb[i] = (kr < K && cg < N) ? B[(size_t)kr * ldb + cg + s] : 0.f;
            }
        }
#pragma unroll
        for (int kk = 0; kk < 8; kk++) {
            float4 a0 = *(const float4*)&As[buf][kk][ty * 8];
            float4 a1 = *(const float4*)&As[buf][kk][ty * 8 + 4];
            float4 b0 = *(const float4*)&Bs[buf][kk][tx * 8];
            float4 b1 = *(const float4*)&Bs[buf][kk][tx * 8 + 4];
            float av[8] = {a0.x, a0.y, a0.z, a0.w, a1.x, a1.y, a1.z, a1.w};
            float bv[8] = {b0.x, b0.y, b0.z, b0.w, b1.x, b1.y, b1.z, b1.w};
#pragma unroll
            for (int i = 0; i < 8; i++)
#pragma unroll
                for (int j = 0; j < 8; j++) acc[i][j] += av[i] * bv[j];
        }
        if (tn < total) {
            buf ^= 1;
            As[buf][ac + 0][ar] = pa.x;
            As[buf][ac + 1][ar] = pa.y;
            As[buf][ac + 2][ar] = pa.z;
            As[buf][ac + 3][ar] = pa.w;
#pragma unroll
            for (int i = 0; i < 4; i++) {
                int idx = tid + (i << 8);
                Bs[buf][idx >> 7][idx & 127] = pb[i];
            }
            __syncthreads();
        }
    }

    // ---- epilogue ----
#pragma unroll
    for (int i = 0; i < 8; i++) {
        int r = row0 + ty * 8 + i;
        if (r >= M) continue;
        float rb = (BMODE == 3) ? bias[r] : 0.f;
#pragma unroll
        for (int j4 = 0; j4 < 8; j4 += 4) {
            int c = col0 + tx * 8 + j4;
            if (c < N) {
                float4 v;
                v.x = acc[i][j4 + 0];
                v.y = acc[i][j4 + 1];
                v.z = acc[i][j4 + 2];
                v.w = acc[i][j4 + 3];
                if (BMODE == 1) {
                    v.x += bias[c]; v.y += bias[c + 1]; v.z += bias[c + 2]; v.w += bias[c + 3];
                } else if (BMODE == 2) {
                    const float* bp = bias + (size_t)r * N + c;
                    v.x += bp[0]; v.y += bp[1]; v.z += bp[2]; v.w += bp[3];
                } else if (BMODE == 3) {
                    v.x += rb; v.y += rb; v.z += rb; v.w += rb;
                }
                *(float4*)(C + (size_t)r * ldc + c) = v;
            }
        }
    }
}

static void run_gemm(const float* A, const float* B, float* C, const float* bias,
                     int M, int N, int K, int lda, int ldb, int ldc,
                     int bmode, int nsplit, int aStep)
{
    dim3 grid((N + 127) / 128, (M + 127) / 128);
    if (nsplit == 3) {
        switch (bmode) {
            case 0: gemm_k<0,3><<<grid,256>>>(A,B,C,bias,M,N,K,lda,ldb,ldc,aStep); break;
            case 1: gemm_k<1,3><<<grid,256>>>(A,B,C,bias,M,N,K,lda,ldb,ldc,aStep); break;
            case 2: gemm_k<2,3><<<grid,256>>>(A,B,C,bias,M,N,K,lda,ldb,ldc,aStep); break;
            default:gemm_k<3,3><<<grid,256>>>(A,B,C,bias,M,N,K,lda,ldb,ldc,aStep); break;
        }
    } else {
        switch (bmode) {
            case 0: gemm_k<0,1><<<grid,256>>>(A,B,C,bias,M,N,K,lda,ldb,ldc,aStep); break;
            case 1: gemm_k<1,1><<<grid,256>>>(A,B,C,bias,M,N,K,lda,ldb,ldc,aStep); break;
            case 2: gemm_k<2,1><<<grid,256>>>(A,B,C,bias,M,N,K,lda,ldb,ldc,aStep); break;
            default:gemm_k<3,1><<<grid,256>>>(A,B,C,bias,M,N,K,lda,ldb,ldc,aStep); break;
        }
    }
}

// GRU gates (vectorized float4)
__global__ void gates_k(const float* __restrict__ hin, float* __restrict__ hout) {
    int idx = blockIdx.x * blockDim.x + threadIdx.x;
    if (idx < NTOT * 50) {
        int n = idx / 50, q = idx % 50;
        size_t g4 = (size_t)n * 150 + q;
        const float4* gi4 = (const float4*)d_gi;
        const float4* gh4 = (const float4*)d_gh;
        float4 ir4 = gi4[g4],        hr4 = gh4[g4];
        float4 iz4 = gi4[g4 + 50],   hz4 = gh4[g4 + 50];
        float4 in4 = gi4[g4 + 100],  hn4 = gh4[g4 + 100];
        float4 h4  = ((const float4*)hin)[(size_t)n * 50 + q];
        float4 o;
        {
            float r = 1.f / (1.f + __expf(-(ir4.x + hr4.x)));
            float z = 1.f / (1.f + __expf(-(iz4.x + hz4.x)));
            float nn = tanhf(in4.x + r * hn4.x);
            o.x = (1.f - z) * nn + z * h4.x;
        }
        {
            float r = 1.f / (1.f + __expf(-(ir4.y + hr4.y)));
            float z = 1.f / (1.f + __expf(-(iz4.y + hz4.y)));
            float nn = tanhf(in4.y + r * hn4.y);
            o.y = (1.f - z) * nn + z * h4.y;
        }
        {
            float r = 1.f / (1.f + __expf(-(ir4.z + hr4.z)));
            float z = 1.f / (1.f + __expf(-(iz4.z + hz4.z)));
            float nn = tanhf(in4.z + r * hn4.z);
            o.z = (1.f - z) * nn + z * h4.z;
        }
        {
            float r = 1.f / (1.f + __expf(-(ir4.w + hr4.w)));
            float z = 1.f / (1.f + __expf(-(iz4.w + hz4.w)));
            float nn = tanhf(in4.w + r * hn4.w);
            o.w = (1.f - z) * nn + z * h4.w;
        }
        ((float4*)hout)[(size_t)n * 50 + q] = o;
    }
}

// in [G][C] -> out [C][G]
__global__ void transpose_k(const float* __restrict__ in, float* __restrict__ out,
                            int G, int C) {
    __shared__ float tile[32][33];
    int c0 = blockIdx.x * 32;
    int g0 = blockIdx.y * 32;
    int c = c0 + threadIdx.x;
#pragma unroll
    for (int j = 0; j < 32; j += 8) {
        int g = g0 + threadIdx.y + j;
        tile[threadIdx.y + j][threadIdx.x] = (c < C && g < G) ? in[(size_t)g * C + c] : 0.f;
    }
    __syncthreads();
    int g = g0 + threadIdx.x;
#pragma unroll
    for (int j = 0; j < 32; j += 8) {
        int cc = c0 + threadIdx.y + j;
        if (cc < C && g < G) out[(size_t)cc * G + g] = tile[threadIdx.x][threadIdx.y + j];
    }
}

// relu+maxpool k3 s2: [C][32768] -> [C][64*254]
__global__ void pool3_k(const float* __restrict__ in, float* __restrict__ out, int C) {
    int idx = blockIdx.x * blockDim.x + threadIdx.x;
    if (idx < C * GP1) {
        int co = idx / GP1;
        int r = idx % GP1;
        int b = r / P1, p = r % P1;
        int base = co * NTOT + b * NPG + 2 * p;
        float m = fmaxf(fmaxf(in[base], in[base + 1]), in[base + 2]);
        out[idx] = fmaxf(m, 0.f);
    }
}

// relu+maxpool k2 s2: [C][64*254] -> [C][64*127]
__global__ void pool2_k(const float* __restrict__ in, float* __restrict__ out, int C) {
    int idx = blockIdx.x * blockDim.x + threadIdx.x;
    if (idx < C * GP2) {
        int co = idx / GP2;
        int r = idx % GP2;
        int b = r / P2, p = r % P2;
        int base = co * GP1 + b * P1 + 2 * p;
        out[idx] = fmaxf(fmaxf(in[base], in[base + 1]), 0.f);
    }
}

// (ly + by) * (lz + bz), mean over 127, softmax over 7
__global__ void final_k(const float* __restrict__ by, const float* __restrict__ bz,
                        float* __restrict__ out) {
    __shared__ float red[NCLS][128];
    int b = blockIdx.x;
    int tid = threadIdx.x;
    float part[NCLS] = {};
    for (int p = tid; p < P2; p += blockDim.x) {
        int base = b * P2 + p;
#pragma unroll
        for (int cl = 0; cl < NCLS; cl++) {
            float y = d_ly[cl * GP2 + base] + by[cl];
            float z = d_lz[cl * GP2 + base] + bz[cl];
            part[cl] += y * z;
        }
    }
#pragma unroll
    for (int cl = 0; cl < NCLS; cl++) red[cl][tid] = part[cl];
    __syncthreads();
    if (tid == 0) {
        float v[NCLS];
        for (int cl = 0; cl < NCLS; cl++) {
            float s = 0.f;
            for (int i = 0; i < 128; i++) s += red[cl][i];
            v[cl] = s / (float)P2;
        }
        float mx = v[0];
        for (int cl = 1; cl < NCLS; cl++) mx = fmaxf(mx, v[cl]);
        float se = 0.f;
        for (int cl = 0; cl < NCLS; cl++) { v[cl] = __expf(v[cl] - mx); se += v[cl]; }
        for (int cl = 0; cl < NCLS; cl++) out[b * NCLS + cl] = v[cl] / se;
    }
}

// ----------------------------- host side ----------------------------------
static void* getsym(const void* s) {
    void* p = nullptr;
    cudaGetSymbolAddress(&p, s);
    return p;
}

extern "C" void kernel_launch(void* const* d_in, const int* in_sizes, int n_in,
                              void* d_out, int out_size)
{
    const float* features = (const float*)d_in[0];
    const int*   esrc     = (const int*)  d_in[1];
    const int*   edst     = (const int*)  d_in[2];
    const int*   etyp     = (const int*)  d_in[3];
    const float* etype_W  = (const float*)d_in[4];
    const float* etype_b  = (const float*)d_in[5];
    const float* W_ih     = (const float*)d_in[6];
    const float* b_ih     = (const float*)d_in[7];
    const float* W_hh     = (const float*)d_in[8];
    const float* b_hh     = (const float*)d_in[9];
    const float* conv1_w  = (const float*)d_in[10];
    const float* conv1_b  = (const float*)d_in[11];
    const float* conv2_w  = (const float*)d_in[12];
    const float* conv2_b  = (const float*)d_in[13];
    const float* convc1_w = (const float*)d_in[14];
    const float* convc1_b = (const float*)d_in[15];
    const float* convc2_w = (const float*)d_in[16];
    const float* convc2_b = (const float*)d_in[17];
    const float* mlp_y_w  = (const float*)d_in[18];
    const float* mlp_y_b  = (const float*)d_in[19];
    const float* mlp_z_w  = (const float*)d_in[20];
    const float* mlp_z_b  = (const float*)d_in[21];

    float* p_h0   = (float*)getsym(d_h0);
    float* p_h1   = (float*)getsym(d_h1);
    float* p_Amat = (float*)getsym(d_Amat);
    float* p_amsg = (float*)getsym(d_amsg);
    float* p_gi   = (float*)getsym(d_gi);
    float* p_gh   = (float*)getsym(d_gh);
    float* p_Wst  = (float*)getsym(d_Wstack);
    float* p_WihT = (float*)getsym(d_WihT);
    float* p_WhhT = (float*)getsym(d_WhhT);
    float* p_nb   = (float*)getsym(d_nbias);
    int*   p_deg4 = (int*)  getsym(d_deg4);
    float* p_cT   = (float*)getsym(d_cT);
    float* p_w1y  = (float*)getsym(d_w1y);
    float* p_w1z  = (float*)getsym(d_w1z);
    float* p_y1   = (float*)getsym(d_y1);
    float* p_z1   = (float*)getsym(d_z1);
    float* p_yp1  = (float*)getsym(d_yp1);
    float* p_zp1  = (float*)getsym(d_zp1);
    float* p_y2   = (float*)getsym(d_y2);
    float* p_z2   = (float*)getsym(d_z2);
    float* p_yp2  = (float*)getsym(d_yp2);
    float* p_zp2  = (float*)getsym(d_zp2);
    float* p_ly   = (float*)getsym(d_ly);
    float* p_lz   = (float*)getsym(d_lz);

    const int T = 256;

    // ---- setup: deterministic CSR + weight packing + init ----
    zero_int_k<<<(NTOT * 4 + T - 1) / T, T>>>(p_deg4, NTOT * 4);
    hist_k<<<(EDGES + T - 1) / T, T>>>(edst, etyp);
    scan_k<<<1, 1024>>>();
    chunk_hist_k<<<dim3(NCHK, BATCH), 512>>>(edst);
    chunk_scan_k<<<(NTOT + T - 1) / T, T>>>();
    scatter_k<<<dim3(NCHK, BATCH), 512>>>(esrc, edst, etyp);
    pack_wstack_k<<<(4 * ODIM * ODIM + T - 1) / T, T>>>(etype_W);
    pack_T_k<<<(ODIM * H3 + T - 1) / T, T>>>(W_ih, p_WihT);
    pack_T_k<<<(ODIM * H3 + T - 1) / T, T>>>(W_hh, p_WhhT);
    pack_conv_k<<<(3 * ODIM * ODIM + T - 1) / T, T>>>(conv1_w, p_w1y, ODIM);
    pack_conv_k<<<(3 * CDIM * CDIM + T - 1) / T, T>>>(convc1_w, p_w1z, CDIM);
    init_h_k<<<(NTOT * ODIM + T - 1) / T, T>>>(features);
    nodebias_k<<<(NTOT * ODIM + T - 1) / T, T>>>(etype_b);

    // ---- GGNN: 8 steps ----
    for (int s = 0; s < 8; s++) {
        const float* hin  = (s & 1) ? p_h1 : p_h0;
        float*       hout = (s & 1) ? p_h0 : p_h1;
        spmm_k<<<NTOT, 256>>>(hin);
        run_gemm(p_Amat, p_Wst, p_amsg, p_nb, NTOT, ODIM, 800, 800, ODIM, ODIM, 2, 1, 0);
        run_gemm(p_amsg, p_WihT, p_gi, b_ih, NTOT, H3, ODIM, ODIM, H3, H3, 1, 1, 0);
        run_gemm(hin,    p_WhhT, p_gh, b_hh, NTOT, H3, ODIM, ODIM, H3, H3, 1, 1, 0);
        gates_k<<<(NTOT * 50 + T - 1) / T, T>>>(hin, hout);
    }
    float* p_hf = p_h0;  // after 8 steps result is in h0

    // ---- readout ----
    transpose_k<<<dim3((ODIM + 31) / 32, NTOT / 32), dim3(32, 8)>>>(p_hf, p_cT, NTOT, ODIM);
    transpose_k<<<dim3((IDIM + 31) / 32, NTOT / 32), dim3(32, 8)>>>(features, p_cT + (size_t)ODIM * NTOT, NTOT, IDIM);

    // Y branch
    run_gemm(p_w1y, p_cT, p_y1, conv1_b, ODIM, NTOT, ODIM, ODIM, NTOT, NTOT, 3, 3, ODIM * ODIM);
    pool3_k<<<(ODIM * GP1 + T - 1) / T, T>>>(p_y1, p_yp1, ODIM);
    run_gemm(conv2_w, p_yp1, p_y2, conv2_b, ODIM, GP1, ODIM, ODIM, GP1, GP1, 3, 1, 0);
    pool2_k<<<(ODIM * GP2 + T - 1) / T, T>>>(p_y2, p_yp2, ODIM);

    // Z branch
    run_gemm(p_w1z, p_cT, p_z1, convc1_b, CDIM, NTOT, CDIM, CDIM, NTOT, NTOT, 3, 3, CDIM * CDIM);
    pool3_k<<<(CDIM * GP1 + T - 1) / T, T>>>(p_z1, p_zp1, CDIM);
    run_gemm(convc2_w, p_zp1, p_z2, convc2_b, CDIM, GP1, CDIM, CDIM, GP1, GP1, 3, 1, 0);
    pool2_k<<<(CDIM * GP2 + T - 1) / T, T>>>(p_z2, p_zp2, CDIM);

    // gating MLPs (bias added in final kernel)
    run_gemm(mlp_y_w, p_yp2, p_ly, nullptr, NCLS, GP2, ODIM, ODIM, GP2, GP2, 0, 1, 0);
    run_gemm(mlp_z_w, p_zp2, p_lz, nullptr, NCLS, GP2, CDIM, CDIM, GP2, GP2, 0, 1, 0);

    final_k<<<BATCH, 128>>>(mlp_y_b, mlp_z_b, (float*)d_out);
}

// round 3
// speedup vs baseline: 1.4583x; 1.3730x over previous
#include <cuda_runtime.h>

#define BATCH  64
#define NPG    512
#define NTOT   32768
#define EDGES  524288
#define EPG    8192
#define NCHK   16
#define ODIM   200
#define IDIM   100
#define H3     600
#define CDIM   300
#define P1     254
#define P2     127
#define GP1    16256
#define GP2    8128
#define NCLS   7

// ----------------------------- device scratch -----------------------------
__device__ float d_h0[NTOT*ODIM];
__device__ float d_h1[NTOT*ODIM];
__device__ float d_Amat[NTOT*4*ODIM];
__device__ float d_amsg[NTOT*ODIM];
__device__ float d_gi[NTOT*H3];
__device__ float d_gh[NTOT*H3];
__device__ float d_Wstack[4*ODIM*ODIM];
__device__ float d_WihT[ODIM*H3];
__device__ float d_WhhT[ODIM*H3];
__device__ float d_nbias[NTOT*ODIM];
__device__ int   d_deg4[NTOT*4];
__device__ int   d_indptr[NTOT+1];
__device__ int   d_ccnt[NTOT*NCHK];
__device__ int   d_srcs[EDGES];
__device__ int   d_typs[EDGES];
__device__ float d_cT[CDIM*NTOT + 64];
__device__ float d_w1y[3*ODIM*ODIM];
__device__ float d_w1z[3*CDIM*CDIM];
__device__ float d_y1[ODIM*NTOT];
__device__ float d_z1[CDIM*NTOT];
__device__ float d_yp1[ODIM*GP1];
__device__ float d_zp1[CDIM*GP1];
__device__ float d_y2[ODIM*GP1];
__device__ float d_z2[CDIM*GP1];
__device__ float d_yp2[ODIM*GP2];
__device__ float d_zp2[CDIM*GP2];
__device__ float d_ly[NCLS*GP2];
__device__ float d_lz[NCLS*GP2];

// ----------------------------- setup kernels ------------------------------
__global__ void zero_int_k(int* p, int n) {
    int i = blockIdx.x * blockDim.x + threadIdx.x;
    if (i < n) p[i] = 0;
}

__global__ void hist_k(const int* __restrict__ edst, const int* __restrict__ etyp) {
    int e = blockIdx.x * blockDim.x + threadIdx.x;
    if (e < EDGES) atomicAdd(&d_deg4[edst[e] * 4 + etyp[e]], 1);
}

__global__ void scan_k() {
    __shared__ int ssum[1024];
    int t = threadIdx.x;
    int loc[32];
    int s = 0;
#pragma unroll
    for (int i = 0; i < 32; i++) {
        int n = t * 32 + i;
        int d = d_deg4[n*4] + d_deg4[n*4+1] + d_deg4[n*4+2] + d_deg4[n*4+3];
        loc[i] = s; s += d;
    }
    ssum[t] = s;
    __syncthreads();
    if (t == 0) {
        int acc = 0;
        for (int i = 0; i < 1024; i++) { int v = ssum[i]; ssum[i] = acc; acc += v; }
        d_indptr[NTOT] = acc;
    }
    __syncthreads();
    int off = ssum[t];
#pragma unroll
    for (int i = 0; i < 32; i++) d_indptr[t * 32 + i] = off + loc[i];
}

__global__ void chunk_hist_k(const int* __restrict__ edst) {
    __shared__ int h[NPG];
    int g = blockIdx.y, c = blockIdx.x;
    h[threadIdx.x] = 0;
    __syncthreads();
    int e = g * EPG + c * 512 + threadIdx.x;
    atomicAdd(&h[edst[e] - g * NPG], 1);
    __syncthreads();
    d_ccnt[(g * NPG + threadIdx.x) * NCHK + c] = h[threadIdx.x];
}

__global__ void chunk_scan_k() {
    int n = blockIdx.x * blockDim.x + threadIdx.x;
    if (n < NTOT) {
        int base = d_indptr[n];
#pragma unroll
        for (int c = 0; c < NCHK; c++) {
            int v = d_ccnt[n * NCHK + c];
            d_ccnt[n * NCHK + c] = base;
            base += v;
        }
    }
}

__global__ void scatter_k(const int* __restrict__ esrc, const int* __restrict__ edst,
                          const int* __restrict__ etyp) {
    __shared__ int sd[512];
    int g = blockIdx.y, c = blockIdx.x;
    int e = g * EPG + c * 512 + threadIdx.x;
    int dl = edst[e] - g * NPG;
    sd[threadIdx.x] = dl;
    __syncthreads();
    int rank = 0;
    for (int i = 0; i < threadIdx.x; i++) rank += (sd[i] == dl);
    int pos = d_ccnt[(g * NPG + dl) * NCHK + c] + rank;
    d_srcs[pos] = esrc[e];
    d_typs[pos] = etyp[e];
}

__global__ void pack_wstack_k(const float* __restrict__ W) {
    int idx = blockIdx.x * blockDim.x + threadIdx.x;
    if (idx < 4 * ODIM * ODIM) {
        int o = idx % ODIM;
        int d = (idx / ODIM) % ODIM;
        int t = idx / (ODIM * ODIM);
        d_Wstack[(t * ODIM + d) * ODIM + o] = W[(t * ODIM + o) * ODIM + d];
    }
}

__global__ void pack_T_k(const float* __restrict__ W, float* __restrict__ out) {
    int idx = blockIdx.x * blockDim.x + threadIdx.x;
    if (idx < ODIM * H3) {
        int j = idx % H3;
        int d = idx / H3;
        out[d * H3 + j] = W[j * ODIM + d];
    }
}

__global__ void pack_conv_k(const float* __restrict__ W, float* __restrict__ out, int C) {
    int idx = blockIdx.x * blockDim.x + threadIdx.x;
    if (idx < 3 * C * C) {
        int ci = idx % C;
        int co = (idx / C) % C;
        int k  = idx / (C * C);
        out[idx] = W[(co * C + ci) * 3 + k];
    }
}

__global__ void init_h_k(const float* __restrict__ feat) {
    int idx = blockIdx.x * blockDim.x + threadIdx.x;
    if (idx < NTOT * ODIM) {
        int d = idx % ODIM;
        int n = idx / ODIM;
        d_h0[idx] = (d < IDIM) ? feat[n * IDIM + d] : 0.f;
    }
}

__global__ void nodebias_k(const float* __restrict__ eb) {
    int idx = blockIdx.x * blockDim.x + threadIdx.x;
    if (idx < NTOT * ODIM) {
        int o = idx % ODIM;
        int n = idx / ODIM;
        float s = 0.f;
#pragma unroll
        for (int t = 0; t < 4; t++) s += (float)d_deg4[n * 4 + t] * eb[t * ODIM + o];
        d_nbias[idx] = s;
    }
}

__global__ void spmm_k(const float* __restrict__ h) {
    __shared__ int ss[128], st[128];
    int n = blockIdx.x;
    int tid = threadIdx.x;
    int beg = d_indptr[n], end = d_indptr[n + 1];
    float a0 = 0.f, a1 = 0.f, a2 = 0.f, a3 = 0.f;
    for (int base = beg; base < end; base += 128) {
        int cnt = min(128, end - base);
        if (tid < cnt) { ss[tid] = d_srcs[base + tid]; st[tid] = d_typs[base + tid]; }
        __syncthreads();
        if (tid < ODIM) {
            for (int e = 0; e < cnt; e++) {
                float v = h[ss[e] * ODIM + tid];
                int t = st[e];
                a0 += (t == 0) ? v : 0.f;
                a1 += (t == 1) ? v : 0.f;
                a2 += (t == 2) ? v : 0.f;
                a3 += (t == 3) ? v : 0.f;
            }
        }
        __syncthreads();
    }
    if (tid < ODIM) {
        float* Ar = &d_Amat[(size_t)n * 800];
        Ar[tid]       = a0;
        Ar[200 + tid] = a1;
        Ar[400 + tid] = a2;
        Ar[600 + tid] = a3;
    }
}

// --------------------------- tensor-core GEMM ------------------------------
// 3xTF32: C = A*B with each operand split hi/lo in tf32, fp32 accumulate.
// C[M,N] = sum_s A_s[M,K]*B_s[K,N] (+bias). A_s = A + s*aStep, B_s = B + s.
// BMODE: 0 none, 1 bias[col], 2 bias matrix [M,N] (ld=N), 3 bias[row]

__device__ __forceinline__ unsigned f2tf32(float f) {
    unsigned u;
    asm("cvt.rna.tf32.f32 %0, %1;" : "=r"(u) : "f"(f));
    return u;
}

__device__ __forceinline__ void mma_tf32(float* d, const unsigned* a, const unsigned* b) {
    asm volatile(
        "mma.sync.aligned.m16n8k8.row.col.f32.tf32.tf32.f32 "
        "{%0,%1,%2,%3}, {%4,%5,%6,%7}, {%8,%9}, {%0,%1,%2,%3};"
        : "+f"(d[0]), "+f"(d[1]), "+f"(d[2]), "+f"(d[3])
        : "r"(a[0]), "r"(a[1]), "r"(a[2]), "r"(a[3]), "r"(b[0]), "r"(b[1]));
}

template<int BMODE, int NSPLIT>
__global__ __launch_bounds__(256, 2) void gemm_tc(
    const float* __restrict__ A, const float* __restrict__ B,
    float* __restrict__ C, const float* __restrict__ bias,
    int M, int N, int K, int lda, int ldb, int ldc, int aStep)
{
    // A fragments: [k2][mb][lane][reg], 16B-contiguous per lane -> LDS.128
    __shared__ unsigned AsHi[2][8][32][4];
    __shared__ unsigned AsLo[2][8][32][4];
    // B fragments: [k2][nb][lane*2+reg] with 66-stride padding (bank-safe)
    __shared__ unsigned BsHi[2][16][66];
    __shared__ unsigned BsLo[2][16][66];

    const int tid  = threadIdx.x;
    const int lane = tid & 31;
    const int w    = tid >> 5;
    const int wm   = w & 3;   // 4 warps over M (32 rows each)
    const int wn   = w >> 2;  // 2 warps over N (64 cols each)
    const int row0 = blockIdx.y * 128;
    const int col0 = blockIdx.x * 128;

    // --- B staging coords: thread -> (krow, 8 cols) ---
    const int s_krow = tid >> 4;         // 0..15
    const int s_cb   = (tid & 15) * 8;   // col base
    const int s_bk2  = s_krow >> 3;
    const int s_kl   = s_krow & 7;
    const int s_j    = (s_kl >> 2) & 1;
    const int s_km   = s_kl & 3;

    float acc[2][8][4];
#pragma unroll
    for (int mt = 0; mt < 2; mt++)
#pragma unroll
        for (int nt = 0; nt < 8; nt++)
#pragma unroll
            for (int i = 0; i < 4; i++) acc[mt][nt][i] = 0.f;

    const int ktiles = (K + 15) >> 4;
    const int total  = ktiles * NSPLIT;

    for (int t = 0; t < total; t++) {
        const int sI = (NSPLIT == 1) ? 0 : (t / ktiles);
        const int kt = (NSPLIT == 1) ? t : (t % ktiles);
        const int k0 = kt << 4;
        const float* Ap = A + (size_t)sI * aStep;

        // ---- stage A: each thread fills 2 fragment lane-slots (4 elems each) ----
#pragma unroll
        for (int sl = 0; sl < 2; sl++) {
            int slot = tid + (sl << 8);            // 0..511
            int k2   = slot >> 8;
            int mb   = (slot >> 5) & 7;
            int ln   = slot & 31;
            int r    = ln >> 2;                    // 0..7
            int cc   = ln & 3;                     // 0..3
            int gr0  = row0 + mb * 16 + r;
            int gr1  = gr0 + 8;
            int gc0  = k0 + k2 * 8 + cc;
            int gc1  = gc0 + 4;
            bool c0ok = gc0 < K, c1ok = gc1 < K;
            float f0 = (gr0 < M && c0ok) ? Ap[(size_t)gr0 * lda + gc0] : 0.f;
            float f1 = (gr1 < M && c0ok) ? Ap[(size_t)gr1 * lda + gc0] : 0.f;
            float f2 = (gr0 < M && c1ok) ? Ap[(size_t)gr0 * lda + gc1] : 0.f;
            float f3 = (gr1 < M && c1ok) ? Ap[(size_t)gr1 * lda + gc1] : 0.f;
            unsigned h0 = f2tf32(f0), h1 = f2tf32(f1), h2 = f2tf32(f2), h3 = f2tf32(f3);
            uint4 hv; hv.x = h0; hv.y = h1; hv.z = h2; hv.w = h3;
            uint4 lv;
            lv.x = f2tf32(f0 - __uint_as_float(h0));
            lv.y = f2tf32(f1 - __uint_as_float(h1));
            lv.z = f2tf32(f2 - __uint_as_float(h2));
            lv.w = f2tf32(f3 - __uint_as_float(h3));
            *(uint4*)&AsHi[k2][mb][ln][0] = hv;
            *(uint4*)&AsLo[k2][mb][ln][0] = lv;
        }

        // ---- stage B: 8 scalars per thread ----
        {
            int gk = k0 + s_krow;
            bool kok = gk < K;
            const float* Bp = B + (size_t)gk * ldb + sI + col0;
#pragma unroll
            for (int c = 0; c < 8; c++) {
                int col = s_cb + c;
                int nb  = col >> 3;
                int li  = ((col & 7) * 4 + s_km) * 2 + s_j;
                float f = (kok && col0 + col < N) ? Bp[col] : 0.f;
                unsigned hi = f2tf32(f);
                BsHi[s_bk2][nb][li] = hi;
                BsLo[s_bk2][nb][li] = f2tf32(f - __uint_as_float(hi));
            }
        }
        __syncthreads();

        // ---- compute ----
#pragma unroll
        for (int k2 = 0; k2 < 2; k2++) {
            unsigned ah[2][4], al[2][4];
#pragma unroll
            for (int mt = 0; mt < 2; mt++) {
                *(uint4*)ah[mt] = *(const uint4*)&AsHi[k2][wm * 2 + mt][lane][0];
                *(uint4*)al[mt] = *(const uint4*)&AsLo[k2][wm * 2 + mt][lane][0];
            }
#pragma unroll
            for (int nt = 0; nt < 8; nt++) {
                unsigned bh[2], bl[2];
                *(uint2*)bh = *(const uint2*)&BsHi[k2][wn * 8 + nt][lane * 2];
                *(uint2*)bl = *(const uint2*)&BsLo[k2][wn * 8 + nt][lane * 2];
#pragma unroll
                for (int mt = 0; mt < 2; mt++) {
                    mma_tf32(acc[mt][nt], ah[mt], bl);
                    mma_tf32(acc[mt][nt], al[mt], bh);
                    mma_tf32(acc[mt][nt], ah[mt], bh);
                }
            }
        }
        __syncthreads();
    }

    // ---- epilogue ----
    const int gid = lane >> 2, tig = lane & 3;
#pragma unroll
    for (int mt = 0; mt < 2; mt++) {
#pragma unroll
        for (int half = 0; half < 2; half++) {
            int r = row0 + wm * 32 + mt * 16 + half * 8 + gid;
            if (r >= M) continue;
            float rb = (BMODE == 3) ? bias[r] : 0.f;
#pragma unroll
            for (int nt = 0; nt < 8; nt++) {
                int c = col0 + wn * 64 + nt * 8 + tig * 2;
                if (c >= N) continue;
                float v0 = acc[mt][nt][half * 2 + 0];
                float v1 = acc[mt][nt][half * 2 + 1];
                if (BMODE == 1)      { v0 += bias[c]; v1 += bias[c + 1]; }
                else if (BMODE == 2) { v0 += bias[(size_t)r * N + c]; v1 += bias[(size_t)r * N + c + 1]; }
                else if (BMODE == 3) { v0 += rb; v1 += rb; }
                float2 o; o.x = v0; o.y = v1;
                *(float2*)(C + (size_t)r * ldc + c) = o;
            }
        }
    }
}

static void run_gemm(const float* A, const float* B, float* C, const float* bias,
                     int M, int N, int K, int lda, int ldb, int ldc,
                     int bmode, int nsplit, int aStep)
{
    dim3 grid((N + 127) / 128, (M + 127) / 128);
    if (nsplit == 3) {
        switch (bmode) {
            case 0: gemm_tc<0,3><<<grid,256>>>(A,B,C,bias,M,N,K,lda,ldb,ldc,aStep); break;
            case 1: gemm_tc<1,3><<<grid,256>>>(A,B,C,bias,M,N,K,lda,ldb,ldc,aStep); break;
            case 2: gemm_tc<2,3><<<grid,256>>>(A,B,C,bias,M,N,K,lda,ldb,ldc,aStep); break;
            default:gemm_tc<3,3><<<grid,256>>>(A,B,C,bias,M,N,K,lda,ldb,ldc,aStep); break;
        }
    } else {
        switch (bmode) {
            case 0: gemm_tc<0,1><<<grid,256>>>(A,B,C,bias,M,N,K,lda,ldb,ldc,aStep); break;
            case 1: gemm_tc<1,1><<<grid,256>>>(A,B,C,bias,M,N,K,lda,ldb,ldc,aStep); break;
            case 2: gemm_tc<2,1><<<grid,256>>>(A,B,C,bias,M,N,K,lda,ldb,ldc,aStep); break;
            default:gemm_tc<3,1><<<grid,256>>>(A,B,C,bias,M,N,K,lda,ldb,ldc,aStep); break;
        }
    }
}

// GRU gates (vectorized float4)
__global__ void gates_k(const float* __restrict__ hin, float* __restrict__ hout) {
    int idx = blockIdx.x * blockDim.x + threadIdx.x;
    if (idx < NTOT * 50) {
        int n = idx / 50, q = idx % 50;
        size_t g4 = (size_t)n * 150 + q;
        const float4* gi4 = (const float4*)d_gi;
        const float4* gh4 = (const float4*)d_gh;
        float4 ir4 = gi4[g4],        hr4 = gh4[g4];
        float4 iz4 = gi4[g4 + 50],   hz4 = gh4[g4 + 50];
        float4 in4 = gi4[g4 + 100],  hn4 = gh4[g4 + 100];
        float4 h4  = ((const float4*)hin)[(size_t)n * 50 + q];
        float4 o;
        {
            float r = 1.f / (1.f + __expf(-(ir4.x + hr4.x)));
            float z = 1.f / (1.f + __expf(-(iz4.x + hz4.x)));
            float nn = tanhf(in4.x + r * hn4.x);
            o.x = (1.f - z) * nn + z * h4.x;
        }
        {
            float r = 1.f / (1.f + __expf(-(ir4.y + hr4.y)));
            float z = 1.f / (1.f + __expf(-(iz4.y + hz4.y)));
            float nn = tanhf(in4.y + r * hn4.y);
            o.y = (1.f - z) * nn + z * h4.y;
        }
        {
            float r = 1.f / (1.f + __expf(-(ir4.z + hr4.z)));
            float z = 1.f / (1.f + __expf(-(iz4.z + hz4.z)));
            float nn = tanhf(in4.z + r * hn4.z);
            o.z = (1.f - z) * nn + z * h4.z;
        }
        {
            float r = 1.f / (1.f + __expf(-(ir4.w + hr4.w)));
            float z = 1.f / (1.f + __expf(-(iz4.w + hz4.w)));
            float nn = tanhf(in4.w + r * hn4.w);
            o.w = (1.f - z) * nn + z * h4.w;
        }
        ((float4*)hout)[(size_t)n * 50 + q] = o;
    }
}

__global__ void transpose_k(const float* __restrict__ in, float* __restrict__ out,
                            int G, int C) {
    __shared__ float tile[32][33];
    int c0 = blockIdx.x * 32;
    int g0 = blockIdx.y * 32;
    int c = c0 + threadIdx.x;
#pragma unroll
    for (int j = 0; j < 32; j += 8) {
        int g = g0 + threadIdx.y + j;
        tile[threadIdx.y + j][threadIdx.x] = (c < C && g < G) ? in[(size_t)g * C + c] : 0.f;
    }
    __syncthreads();
    int g = g0 + threadIdx.x;
#pragma unroll
    for (int j = 0; j < 32; j += 8) {
        int cc = c0 + threadIdx.y + j;
        if (cc < C && g < G) out[(size_t)cc * G + g] = tile[threadIdx.x][threadIdx.y + j];
    }
}

__global__ void pool3_k(const float* __restrict__ in, float* __restrict__ out, int C) {
    int idx = blockIdx.x * blockDim.x + threadIdx.x;
    if (idx < C * GP1) {
        int co = idx / GP1;
        int r = idx % GP1;
        int b = r / P1, p = r % P1;
        int base = co * NTOT + b * NPG + 2 * p;
        float m = fmaxf(fmaxf(in[base], in[base + 1]), in[base + 2]);
        out[idx] = fmaxf(m, 0.f);
    }
}

__global__ void pool2_k(const float* __restrict__ in, float* __restrict__ out, int C) {
    int idx = blockIdx.x * blockDim.x + threadIdx.x;
    if (idx < C * GP2) {
        int co = idx / GP2;
        int r = idx % GP2;
        int b = r / P2, p = r % P2;
        int base = co * GP1 + b * P1 + 2 * p;
        out[idx] = fmaxf(fmaxf(in[base], in[base + 1]), 0.f);
    }
}

__global__ void final_k(const float* __restrict__ by, const float* __restrict__ bz,
                        float* __restrict__ out) {
    __shared__ float red[NCLS][128];
    int b = blockIdx.x;
    int tid = threadIdx.x;
    float part[NCLS] = {};
    for (int p = tid; p < P2; p += blockDim.x) {
        int base = b * P2 + p;
#pragma unroll
        for (int cl = 0; cl < NCLS; cl++) {
            float y = d_ly[cl * GP2 + base] + by[cl];
            float z = d_lz[cl * GP2 + base] + bz[cl];
            part[cl] += y * z;
        }
    }
#pragma unroll
    for (int cl = 0; cl < NCLS; cl++) red[cl][tid] = part[cl];
    __syncthreads();
    if (tid == 0) {
        float v[NCLS];
        for (int cl = 0; cl < NCLS; cl++) {
            float s = 0.f;
            for (int i = 0; i < 128; i++) s += red[cl][i];
            v[cl] = s / (float)P2;
        }
        float mx = v[0];
        for (int cl = 1; cl < NCLS; cl++) mx = fmaxf(mx, v[cl]);
        float se = 0.f;
        for (int cl = 0; cl < NCLS; cl++) { v[cl] = __expf(v[cl] - mx); se += v[cl]; }
        for (int cl = 0; cl < NCLS; cl++) out[b * NCLS + cl] = v[cl] / se;
    }
}

// ----------------------------- host side ----------------------------------
static void* getsym(const void* s) {
    void* p = nullptr;
    cudaGetSymbolAddress(&p, s);
    return p;
}

extern "C" void kernel_launch(void* const* d_in, const int* in_sizes, int n_in,
                              void* d_out, int out_size)
{
    const float* features = (const float*)d_in[0];
    const int*   esrc     = (const int*)  d_in[1];
    const int*   edst     = (const int*)  d_in[2];
    const int*   etyp     = (const int*)  d_in[3];
    const float* etype_W  = (const float*)d_in[4];
    const float* etype_b  = (const float*)d_in[5];
    const float* W_ih     = (const float*)d_in[6];
    const float* b_ih     = (const float*)d_in[7];
    const float* W_hh     = (const float*)d_in[8];
    const float* b_hh     = (const float*)d_in[9];
    const float* conv1_w  = (const float*)d_in[10];
    const float* conv1_b  = (const float*)d_in[11];
    const float* conv2_w  = (const float*)d_in[12];
    const float* conv2_b  = (const float*)d_in[13];
    const float* convc1_w = (const float*)d_in[14];
    const float* convc1_b = (const float*)d_in[15];
    const float* convc2_w = (const float*)d_in[16];
    const float* convc2_b = (const float*)d_in[17];
    const float* mlp_y_w  = (const float*)d_in[18];
    const float* mlp_y_b  = (const float*)d_in[19];
    const float* mlp_z_w  = (const float*)d_in[20];
    const float* mlp_z_b  = (const float*)d_in[21];

    float* p_h0   = (float*)getsym(d_h0);
    float* p_h1   = (float*)getsym(d_h1);
    float* p_Amat = (float*)getsym(d_Amat);
    float* p_amsg = (float*)getsym(d_amsg);
    float* p_gi   = (float*)getsym(d_gi);
    float* p_gh   = (float*)getsym(d_gh);
    float* p_Wst  = (float*)getsym(d_Wstack);
    float* p_WihT = (float*)getsym(d_WihT);
    float* p_WhhT = (float*)getsym(d_WhhT);
    float* p_nb   = (float*)getsym(d_nbias);
    int*   p_deg4 = (int*)  getsym(d_deg4);
    float* p_cT   = (float*)getsym(d_cT);
    float* p_w1y  = (float*)getsym(d_w1y);
    float* p_w1z  = (float*)getsym(d_w1z);
    float* p_y1   = (float*)getsym(d_y1);
    float* p_z1   = (float*)getsym(d_z1);
    float* p_yp1  = (float*)getsym(d_yp1);
    float* p_zp1  = (float*)getsym(d_zp1);
    float* p_y2   = (float*)getsym(d_y2);
    float* p_z2   = (float*)getsym(d_z2);
    float* p_yp2  = (float*)getsym(d_yp2);
    float* p_zp2  = (float*)getsym(d_zp2);
    float* p_ly   = (float*)getsym(d_ly);
    float* p_lz   = (float*)getsym(d_lz);

    const int T = 256;

    // ---- launches 0..3: profiler (launch idx 3) captures the gh GEMM ----
    init_h_k<<<(NTOT * ODIM + T - 1) / T, T>>>(features);                    // 0
    pack_T_k<<<(ODIM * H3 + T - 1) / T, T>>>(W_hh, p_WhhT);                  // 1
    pack_T_k<<<(ODIM * H3 + T - 1) / T, T>>>(W_ih, p_WihT);                  // 2
    run_gemm(p_h0, p_WhhT, p_gh, b_hh, NTOT, H3, ODIM, ODIM, H3, H3, 1, 1, 0); // 3 (step-0 gh)

    // ---- rest of setup ----
    zero_int_k<<<(NTOT * 4 + T - 1) / T, T>>>(p_deg4, NTOT * 4);
    hist_k<<<(EDGES + T - 1) / T, T>>>(edst, etyp);
    scan_k<<<1, 1024>>>();
    chunk_hist_k<<<dim3(NCHK, BATCH), 512>>>(edst);
    chunk_scan_k<<<(NTOT + T - 1) / T, T>>>();
    scatter_k<<<dim3(NCHK, BATCH), 512>>>(esrc, edst, etyp);
    pack_wstack_k<<<(4 * ODIM * ODIM + T - 1) / T, T>>>(etype_W);
    pack_conv_k<<<(3 * ODIM * ODIM + T - 1) / T, T>>>(conv1_w, p_w1y, ODIM);
    pack_conv_k<<<(3 * CDIM * CDIM + T - 1) / T, T>>>(convc1_w, p_w1z, CDIM);
    nodebias_k<<<(NTOT * ODIM + T - 1) / T, T>>>(etype_b);

    // ---- GGNN: 8 steps ----
    for (int s = 0; s < 8; s++) {
        const float* hin  = (s & 1) ? p_h1 : p_h0;
        float*       hout = (s & 1) ? p_h0 : p_h1;
        spmm_k<<<NTOT, 256>>>(hin);
        run_gemm(p_Amat, p_Wst, p_amsg, p_nb, NTOT, ODIM, 800, 800, ODIM, ODIM, 2, 1, 0);
        run_gemm(p_amsg, p_WihT, p_gi, b_ih, NTOT, H3, ODIM, ODIM, H3, H3, 1, 1, 0);
        if (s > 0)
            run_gemm(hin, p_WhhT, p_gh, b_hh, NTOT, H3, ODIM, ODIM, H3, H3, 1, 1, 0);
        gates_k<<<(NTOT * 50 + T - 1) / T, T>>>(hin, hout);
    }
    float* p_hf = p_h0;

    // ---- readout ----
    transpose_k<<<dim3((ODIM + 31) / 32, NTOT / 32), dim3(32, 8)>>>(p_hf, p_cT, NTOT, ODIM);
    transpose_k<<<dim3((IDIM + 31) / 32, NTOT / 32), dim3(32, 8)>>>(features, p_cT + (size_t)ODIM * NTOT, NTOT, IDIM);

    run_gemm(p_w1y, p_cT, p_y1, conv1_b, ODIM, NTOT, ODIM, ODIM, NTOT, NTOT, 3, 3, ODIM * ODIM);
    pool3_k<<<(ODIM * GP1 + T - 1) / T, T>>>(p_y1, p_yp1, ODIM);
    run_gemm(conv2_w, p_yp1, p_y2, conv2_b, ODIM, GP1, ODIM, ODIM, GP1, GP1, 3, 1, 0);
    pool2_k<<<(ODIM * GP2 + T - 1) / T, T>>>(p_y2, p_yp2, ODIM);

    run_gemm(p_w1z, p_cT, p_z1, convc1_b, CDIM, NTOT, CDIM, CDIM, NTOT, NTOT, 3, 3, CDIM * CDIM);
    pool3_k<<<(CDIM * GP1 + T - 1) / T, T>>>(p_z1, p_zp1, CDIM);
    run_gemm(convc2_w, p_zp1, p_z2, convc2_b, CDIM, GP1, CDIM, CDIM, GP1, GP1, 3, 1, 0);
    pool2_k<<<(CDIM * GP2 + T - 1) / T, T>>>(p_z2, p_zp2, CDIM);

    run_gemm(mlp_y_w, p_yp2, p_ly, nullptr, NCLS, GP2, ODIM, ODIM, GP2, GP2, 0, 1, 0);
    run_gemm(mlp_z_w, p_zp2, p_lz, nullptr, NCLS, GP2, CDIM, CDIM, GP2, GP2, 0, 1, 0);

    final_k<<<BATCH, 128>>>(mlp_y_b, mlp_z_b, (float*)d_out);
}

// round 4
// speedup vs baseline: 1.5359x; 1.0532x over previous
#include <cuda_runtime.h>

#define BATCH  64
#define NPG    512
#define NTOT   32768
#define EDGES  524288
#define EPG    8192
#define NCHK   16
#define ODIM   200
#define IDIM   100
#define H3     600
#define CDIM   300
#define P1     254
#define P2     127
#define GP1    16256
#define GP2    8128
#define NCLS   7

// ----------------------------- device scratch -----------------------------
__device__ float d_h0[NTOT*ODIM];
__device__ float d_h1[NTOT*ODIM];
__device__ float d_Amat[NTOT*4*ODIM];
__device__ float d_amsg[NTOT*ODIM];
__device__ float d_gi[NTOT*H3];
__device__ float d_gh[NTOT*H3];
__device__ float d_Wstack[4*ODIM*ODIM];
__device__ float d_WihT[ODIM*H3];
__device__ float d_WhhT[ODIM*H3];
__device__ float d_nbias[NTOT*ODIM];
__device__ int   d_deg4[NTOT*4];
__device__ int   d_indptr[NTOT+1];
__device__ int   d_ccnt[NTOT*NCHK];
__device__ int   d_srcs[EDGES];
__device__ int   d_typs[EDGES];
__device__ float d_cT[CDIM*NTOT + 64];
__device__ float d_w1y[3*ODIM*ODIM];
__device__ float d_w1z[3*CDIM*CDIM];
__device__ float d_y1[ODIM*NTOT];
__device__ float d_z1[CDIM*NTOT];
__device__ float d_yp1[ODIM*GP1];
__device__ float d_zp1[CDIM*GP1];
__device__ float d_y2[ODIM*GP1];
__device__ float d_z2[CDIM*GP1];
__device__ float d_yp2[ODIM*GP2];
__device__ float d_zp2[CDIM*GP2];
__device__ float d_ly[NCLS*GP2];
__device__ float d_lz[NCLS*GP2];

// ----------------------------- setup kernels ------------------------------
__global__ void zero_int_k(int* p, int n) {
    int i = blockIdx.x * blockDim.x + threadIdx.x;
    if (i < n) p[i] = 0;
}

__global__ void hist_k(const int* __restrict__ edst, const int* __restrict__ etyp) {
    int e = blockIdx.x * blockDim.x + threadIdx.x;
    if (e < EDGES) atomicAdd(&d_deg4[edst[e] * 4 + etyp[e]], 1);
}

__global__ void scan_k() {
    __shared__ int ssum[1024];
    int t = threadIdx.x;
    int loc[32];
    int s = 0;
#pragma unroll
    for (int i = 0; i < 32; i++) {
        int n = t * 32 + i;
        int d = d_deg4[n*4] + d_deg4[n*4+1] + d_deg4[n*4+2] + d_deg4[n*4+3];
        loc[i] = s; s += d;
    }
    ssum[t] = s;
    __syncthreads();
    if (t == 0) {
        int acc = 0;
        for (int i = 0; i < 1024; i++) { int v = ssum[i]; ssum[i] = acc; acc += v; }
        d_indptr[NTOT] = acc;
    }
    __syncthreads();
    int off = ssum[t];
#pragma unroll
    for (int i = 0; i < 32; i++) d_indptr[t * 32 + i] = off + loc[i];
}

__global__ void chunk_hist_k(const int* __restrict__ edst) {
    __shared__ int h[NPG];
    int g = blockIdx.y, c = blockIdx.x;
    h[threadIdx.x] = 0;
    __syncthreads();
    int e = g * EPG + c * 512 + threadIdx.x;
    atomicAdd(&h[edst[e] - g * NPG], 1);
    __syncthreads();
    d_ccnt[(g * NPG + threadIdx.x) * NCHK + c] = h[threadIdx.x];
}

__global__ void chunk_scan_k() {
    int n = blockIdx.x * blockDim.x + threadIdx.x;
    if (n < NTOT) {
        int base = d_indptr[n];
#pragma unroll
        for (int c = 0; c < NCHK; c++) {
            int v = d_ccnt[n * NCHK + c];
            d_ccnt[n * NCHK + c] = base;
            base += v;
        }
    }
}

__global__ void scatter_k(const int* __restrict__ esrc, const int* __restrict__ edst,
                          const int* __restrict__ etyp) {
    __shared__ int sd[512];
    int g = blockIdx.y, c = blockIdx.x;
    int e = g * EPG + c * 512 + threadIdx.x;
    int dl = edst[e] - g * NPG;
    sd[threadIdx.x] = dl;
    __syncthreads();
    int rank = 0;
    for (int i = 0; i < threadIdx.x; i++) rank += (sd[i] == dl);
    int pos = d_ccnt[(g * NPG + dl) * NCHK + c] + rank;
    d_srcs[pos] = esrc[e];
    d_typs[pos] = etyp[e];
}

__global__ void pack_wstack_k(const float* __restrict__ W) {
    int idx = blockIdx.x * blockDim.x + threadIdx.x;
    if (idx < 4 * ODIM * ODIM) {
        int o = idx % ODIM;
        int d = (idx / ODIM) % ODIM;
        int t = idx / (ODIM * ODIM);
        d_Wstack[(t * ODIM + d) * ODIM + o] = W[(t * ODIM + o) * ODIM + d];
    }
}

__global__ void pack_T_k(const float* __restrict__ W, float* __restrict__ out) {
    int idx = blockIdx.x * blockDim.x + threadIdx.x;
    if (idx < ODIM * H3) {
        int j = idx % H3;
        int d = idx / H3;
        out[d * H3 + j] = W[j * ODIM + d];
    }
}

__global__ void pack_conv_k(const float* __restrict__ W, float* __restrict__ out, int C) {
    int idx = blockIdx.x * blockDim.x + threadIdx.x;
    if (idx < 3 * C * C) {
        int ci = idx % C;
        int co = (idx / C) % C;
        int k  = idx / (C * C);
        out[idx] = W[(co * C + ci) * 3 + k];
    }
}

__global__ void init_h_k(const float* __restrict__ feat) {
    int idx = blockIdx.x * blockDim.x + threadIdx.x;
    if (idx < NTOT * ODIM) {
        int d = idx % ODIM;
        int n = idx / ODIM;
        d_h0[idx] = (d < IDIM) ? feat[n * IDIM + d] : 0.f;
    }
}

__global__ void nodebias_k(const float* __restrict__ eb) {
    int idx = blockIdx.x * blockDim.x + threadIdx.x;
    if (idx < NTOT * ODIM) {
        int o = idx % ODIM;
        int n = idx / ODIM;
        float s = 0.f;
#pragma unroll
        for (int t = 0; t < 4; t++) s += (float)d_deg4[n * 4 + t] * eb[t * ODIM + o];
        d_nbias[idx] = s;
    }
}

__global__ void spmm_k(const float* __restrict__ h) {
    __shared__ int ss[128], st[128];
    int n = blockIdx.x;
    int tid = threadIdx.x;
    int beg = d_indptr[n], end = d_indptr[n + 1];
    float a0 = 0.f, a1 = 0.f, a2 = 0.f, a3 = 0.f;
    for (int base = beg; base < end; base += 128) {
        int cnt = min(128, end - base);
        if (tid < cnt) { ss[tid] = d_srcs[base + tid]; st[tid] = d_typs[base + tid]; }
        __syncthreads();
        if (tid < ODIM) {
            for (int e = 0; e < cnt; e++) {
                float v = h[ss[e] * ODIM + tid];
                int t = st[e];
                a0 += (t == 0) ? v : 0.f;
                a1 += (t == 1) ? v : 0.f;
                a2 += (t == 2) ? v : 0.f;
                a3 += (t == 3) ? v : 0.f;
            }
        }
        __syncthreads();
    }
    if (tid < ODIM) {
        float* Ar = &d_Amat[(size_t)n * 800];
        Ar[tid]       = a0;
        Ar[200 + tid] = a1;
        Ar[400 + tid] = a2;
        Ar[600 + tid] = a3;
    }
}

// --------------------------- tensor-core GEMM ------------------------------
// 3xTF32 with raw-fp32 smem tiles, cp.async staging, double buffering.
// C[M,N] = sum_s A_s[M,K]*B_s[K,N] (+bias). A_s = A + s*aStep, B_s = B + s.
// BMODE: 0 none, 1 bias[col], 2 bias matrix [M,N], 3 bias[row]

__device__ __forceinline__ unsigned f2tf32(float f) {
    unsigned u;
    asm("cvt.rna.tf32.f32 %0, %1;" : "=r"(u) : "f"(f));
    return u;
}

__device__ __forceinline__ void mma_tf32(float* d, const unsigned* a, const unsigned* b) {
    asm volatile(
        "mma.sync.aligned.m16n8k8.row.col.f32.tf32.tf32.f32 "
        "{%0,%1,%2,%3}, {%4,%5,%6,%7}, {%8,%9}, {%0,%1,%2,%3};"
        : "+f"(d[0]), "+f"(d[1]), "+f"(d[2]), "+f"(d[3])
        : "r"(a[0]), "r"(a[1]), "r"(a[2]), "r"(a[3]), "r"(b[0]), "r"(b[1]));
}

__device__ __forceinline__ void cpa16(void* dst, const void* src, int sb) {
    unsigned sa = (unsigned)__cvta_generic_to_shared(dst);
    asm volatile("cp.async.cg.shared.global [%0], [%1], 16, %2;" :: "r"(sa), "l"(src), "r"(sb));
}
__device__ __forceinline__ void cpa4(void* dst, const void* src, int sb) {
    unsigned sa = (unsigned)__cvta_generic_to_shared(dst);
    asm volatile("cp.async.ca.shared.global [%0], [%1], 4, %2;" :: "r"(sa), "l"(src), "r"(sb));
}

#define APAD 20
#define BPAD 136

template<int BMODE, int NSPLIT>
__global__ __launch_bounds__(256, 2) void gemm_tc(
    const float* __restrict__ A, const float* __restrict__ B,
    float* __restrict__ C, const float* __restrict__ bias,
    int M, int N, int K, int lda, int ldb, int ldc, int aStep)
{
    __shared__ float Asm[2][128][APAD];   // raw fp32, cols 0..15 used
    __shared__ float Bsm[2][16][BPAD];    // raw fp32, cols 0..127 used

    const int tid  = threadIdx.x;
    const int lane = tid & 31;
    const int w    = tid >> 5;
    const int wm   = w & 3;
    const int wn   = w >> 2;
    const int row0 = blockIdx.y * 128;
    const int col0 = blockIdx.x * 128;

    const int ktiles = (K + 15) >> 4;
    const int total  = ktiles * NSPLIT;

    float acc[2][8][4];
#pragma unroll
    for (int mt = 0; mt < 2; mt++)
#pragma unroll
        for (int nt = 0; nt < 8; nt++)
#pragma unroll
            for (int i = 0; i < 4; i++) acc[mt][nt][i] = 0.f;

    // --- staging helpers ---
    auto stage = [&](int t, int b) {
        const int sI = (NSPLIT == 1) ? 0 : (t / ktiles);
        const int kt = (NSPLIT == 1) ? t : (t % ktiles);
        const int k0 = kt << 4;
        const float* Ap = A + (size_t)sI * aStep;
        // A: 128 rows x 16 k, 512 16B chunks
#pragma unroll
        for (int i = 0; i < 2; i++) {
            int ch = tid + (i << 8);
            int row = ch >> 2, part = (ch & 3) << 2;
            int gr = row0 + row, gk = k0 + part;
            int sb = (gr < M && gk < K) ? 16 : 0;
            const float* src = sb ? (Ap + (size_t)gr * lda + gk) : Ap;
            cpa16(&Asm[b][row][part], src, sb);
        }
        if (NSPLIT == 1) {
            // B: 16 rows x 128 cols, 512 16B chunks
#pragma unroll
            for (int i = 0; i < 2; i++) {
                int ch = tid + (i << 8);
                int krow = ch >> 5, cp = (ch & 31) << 2;
                int gk = k0 + krow, gc = col0 + cp;
                int sb = (gk < K && gc < N) ? 16 : 0;
                const float* src = sb ? (B + (size_t)gk * ldb + gc) : B;
                cpa16(&Bsm[b][krow][cp], src, sb);
            }
        } else {
            // shifted B: 4B chunks (src alignment only 4B)
#pragma unroll
            for (int i = 0; i < 8; i++) {
                int ch = tid + (i << 8);
                int krow = ch >> 7, c = ch & 127;
                int gk = k0 + krow, gc = col0 + c;
                int sb = (gk < K && gc < N) ? 4 : 0;
                const float* src = sb ? (B + (size_t)gk * ldb + gc + sI) : B;
                cpa4(&Bsm[b][krow][c], src, sb);
            }
        }
        asm volatile("cp.async.commit_group;");
    };

    stage(0, 0);
    asm volatile("cp.async.wait_group 0;");
    __syncthreads();

    int buf = 0;
    const int r_  = lane >> 2;
    const int cc_ = lane & 3;

    for (int t = 0; t < total; t++) {
        if (t + 1 < total) stage(t + 1, buf ^ 1);

#pragma unroll
        for (int k2 = 0; k2 < 2; k2++) {
            unsigned ah[2][4], al[2][4];
#pragma unroll
            for (int mt = 0; mt < 2; mt++) {
                int rb = wm * 32 + mt * 16;
                float f0 = Asm[buf][rb + r_     ][k2 * 8 + cc_];
                float f1 = Asm[buf][rb + r_ + 8 ][k2 * 8 + cc_];
                float f2 = Asm[buf][rb + r_     ][k2 * 8 + cc_ + 4];
                float f3 = Asm[buf][rb + r_ + 8 ][k2 * 8 + cc_ + 4];
                ah[mt][0] = f2tf32(f0); al[mt][0] = f2tf32(f0 - __uint_as_float(ah[mt][0]));
                ah[mt][1] = f2tf32(f1); al[mt][1] = f2tf32(f1 - __uint_as_float(ah[mt][1]));
                ah[mt][2] = f2tf32(f2); al[mt][2] = f2tf32(f2 - __uint_as_float(ah[mt][2]));
                ah[mt][3] = f2tf32(f3); al[mt][3] = f2tf32(f3 - __uint_as_float(ah[mt][3]));
            }
#pragma unroll
            for (int nt = 0; nt < 8; nt++) {
                int cb = wn * 64 + nt * 8 + r_;
                int kb = k2 * 8 + cc_;
                float g0 = Bsm[buf][kb][cb];
                float g1 = Bsm[buf][kb + 4][cb];
                unsigned bh[2], bl[2];
                bh[0] = f2tf32(g0); bl[0] = f2tf32(g0 - __uint_as_float(bh[0]));
                bh[1] = f2tf32(g1); bl[1] = f2tf32(g1 - __uint_as_float(bh[1]));
#pragma unroll
                for (int mt = 0; mt < 2; mt++) {
                    mma_tf32(acc[mt][nt], ah[mt], bl);
                    mma_tf32(acc[mt][nt], al[mt], bh);
                    mma_tf32(acc[mt][nt], ah[mt], bh);
                }
            }
        }

        if (t + 1 < total) asm volatile("cp.async.wait_group 0;");
        __syncthreads();
        buf ^= 1;
    }

    // ---- epilogue ----
    const int gid = lane >> 2, tig = lane & 3;
#pragma unroll
    for (int mt = 0; mt < 2; mt++) {
#pragma unroll
        for (int half = 0; half < 2; half++) {
            int r = row0 + wm * 32 + mt * 16 + half * 8 + gid;
            if (r >= M) continue;
            float rb = (BMODE == 3) ? bias[r] : 0.f;
#pragma unroll
            for (int nt = 0; nt < 8; nt++) {
                int c = col0 + wn * 64 + nt * 8 + tig * 2;
                if (c >= N) continue;
                float v0 = acc[mt][nt][half * 2 + 0];
                float v1 = acc[mt][nt][half * 2 + 1];
                if (BMODE == 1)      { v0 += bias[c]; v1 += bias[c + 1]; }
                else if (BMODE == 2) { v0 += bias[(size_t)r * N + c]; v1 += bias[(size_t)r * N + c + 1]; }
                else if (BMODE == 3) { v0 += rb; v1 += rb; }
                float2 o; o.x = v0; o.y = v1;
                *(float2*)(C + (size_t)r * ldc + c) = o;
            }
        }
    }
}

static void run_gemm(const float* A, const float* B, float* C, const float* bias,
                     int M, int N, int K, int lda, int ldb, int ldc,
                     int bmode, int nsplit, int aStep)
{
    dim3 grid((N + 127) / 128, (M + 127) / 128);
    if (nsplit == 3) {
        switch (bmode) {
            case 0: gemm_tc<0,3><<<grid,256>>>(A,B,C,bias,M,N,K,lda,ldb,ldc,aStep); break;
            case 1: gemm_tc<1,3><<<grid,256>>>(A,B,C,bias,M,N,K,lda,ldb,ldc,aStep); break;
            case 2: gemm_tc<2,3><<<grid,256>>>(A,B,C,bias,M,N,K,lda,ldb,ldc,aStep); break;
            default:gemm_tc<3,3><<<grid,256>>>(A,B,C,bias,M,N,K,lda,ldb,ldc,aStep); break;
        }
    } else {
        switch (bmode) {
            case 0: gemm_tc<0,1><<<grid,256>>>(A,B,C,bias,M,N,K,lda,ldb,ldc,aStep); break;
            case 1: gemm_tc<1,1><<<grid,256>>>(A,B,C,bias,M,N,K,lda,ldb,ldc,aStep); break;
            case 2: gemm_tc<2,1><<<grid,256>>>(A,B,C,bias,M,N,K,lda,ldb,ldc,aStep); break;
            default:gemm_tc<3,1><<<grid,256>>>(A,B,C,bias,M,N,K,lda,ldb,ldc,aStep); break;
        }
    }
}

// GRU gates (vectorized float4)
__global__ void gates_k(const float* __restrict__ hin, float* __restrict__ hout) {
    int idx = blockIdx.x * blockDim.x + threadIdx.x;
    if (idx < NTOT * 50) {
        int n = idx / 50, q = idx % 50;
        size_t g4 = (size_t)n * 150 + q;
        const float4* gi4 = (const float4*)d_gi;
        const float4* gh4 = (const float4*)d_gh;
        float4 ir4 = gi4[g4],        hr4 = gh4[g4];
        float4 iz4 = gi4[g4 + 50],   hz4 = gh4[g4 + 50];
        float4 in4 = gi4[g4 + 100],  hn4 = gh4[g4 + 100];
        float4 h4  = ((const float4*)hin)[(size_t)n * 50 + q];
        float4 o;
        {
            float r = 1.f / (1.f + __expf(-(ir4.x + hr4.x)));
            float z = 1.f / (1.f + __expf(-(iz4.x + hz4.x)));
            float nn = tanhf(in4.x + r * hn4.x);
            o.x = (1.f - z) * nn + z * h4.x;
        }
        {
            float r = 1.f / (1.f + __expf(-(ir4.y + hr4.y)));
            float z = 1.f / (1.f + __expf(-(iz4.y + hz4.y)));
            float nn = tanhf(in4.y + r * hn4.y);
            o.y = (1.f - z) * nn + z * h4.y;
        }
        {
            float r = 1.f / (1.f + __expf(-(ir4.z + hr4.z)));
            float z = 1.f / (1.f + __expf(-(iz4.z + hz4.z)));
            float nn = tanhf(in4.z + r * hn4.z);
            o.z = (1.f - z) * nn + z * h4.z;
        }
        {
            float r = 1.f / (1.f + __expf(-(ir4.w + hr4.w)));
            float z = 1.f / (1.f + __expf(-(iz4.w + hz4.w)));
            float nn = tanhf(in4.w + r * hn4.w);
            o.w = (1.f - z) * nn + z * h4.w;
        }
        ((float4*)hout)[(size_t)n * 50 + q] = o;
    }
}

__global__ void transpose_k(const float* __restrict__ in, float* __restrict__ out,
                            int G, int C) {
    __shared__ float tile[32][33];
    int c0 = blockIdx.x * 32;
    int g0 = blockIdx.y * 32;
    int c = c0 + threadIdx.x;
#pragma unroll
    for (int j = 0; j < 32; j += 8) {
        int g = g0 + threadIdx.y + j;
        tile[threadIdx.y + j][threadIdx.x] = (c < C && g < G) ? in[(size_t)g * C + c] : 0.f;
    }
    __syncthreads();
    int g = g0 + threadIdx.x;
#pragma unroll
    for (int j = 0; j < 32; j += 8) {
        int cc = c0 + threadIdx.y + j;
        if (cc < C && g < G) out[(size_t)cc * G + g] = tile[threadIdx.x][threadIdx.y + j];
    }
}

__global__ void pool3_k(const float* __restrict__ in, float* __restrict__ out, int C) {
    int idx = blockIdx.x * blockDim.x + threadIdx.x;
    if (idx < C * GP1) {
        int co = idx / GP1;
        int r = idx % GP1;
        int b = r / P1, p = r % P1;
        int base = co * NTOT + b * NPG + 2 * p;
        float m = fmaxf(fmaxf(in[base], in[base + 1]), in[base + 2]);
        out[idx] = fmaxf(m, 0.f);
    }
}

__global__ void pool2_k(const float* __restrict__ in, float* __restrict__ out, int C) {
    int idx = blockIdx.x * blockDim.x + threadIdx.x;
    if (idx < C * GP2) {
        int co = idx / GP2;
        int r = idx % GP2;
        int b = r / P2, p = r % P2;
        int base = co * GP1 + b * P1 + 2 * p;
        out[idx] = fmaxf(fmaxf(in[base], in[base + 1]), 0.f);
    }
}

__global__ void final_k(const float* __restrict__ by, const float* __restrict__ bz,
                        float* __restrict__ out) {
    __shared__ float red[NCLS][128];
    int b = blockIdx.x;
    int tid = threadIdx.x;
    float part[NCLS] = {};
    for (int p = tid; p < P2; p += blockDim.x) {
        int base = b * P2 + p;
#pragma unroll
        for (int cl = 0; cl < NCLS; cl++) {
            float y = d_ly[cl * GP2 + base] + by[cl];
            float z = d_lz[cl * GP2 + base] + bz[cl];
            part[cl] += y * z;
        }
    }
#pragma unroll
    for (int cl = 0; cl < NCLS; cl++) red[cl][tid] = part[cl];
    __syncthreads();
    if (tid == 0) {
        float v[NCLS];
        for (int cl = 0; cl < NCLS; cl++) {
            float s = 0.f;
            for (int i = 0; i < 128; i++) s += red[cl][i];
            v[cl] = s / (float)P2;
        }
        float mx = v[0];
        for (int cl = 1; cl < NCLS; cl++) mx = fmaxf(mx, v[cl]);
        float se = 0.f;
        for (int cl = 0; cl < NCLS; cl++) { v[cl] = __expf(v[cl] - mx); se += v[cl]; }
        for (int cl = 0; cl < NCLS; cl++) out[b * NCLS + cl] = v[cl] / se;
    }
}

// ----------------------------- host side ----------------------------------
static void* getsym(const void* s) {
    void* p = nullptr;
    cudaGetSymbolAddress(&p, s);
    return p;
}

extern "C" void kernel_launch(void* const* d_in, const int* in_sizes, int n_in,
                              void* d_out, int out_size)
{
    const float* features = (const float*)d_in[0];
    const int*   esrc     = (const int*)  d_in[1];
    const int*   edst     = (const int*)  d_in[2];
    const int*   etyp     = (const int*)  d_in[3];
    const float* etype_W  = (const float*)d_in[4];
    const float* etype_b  = (const float*)d_in[5];
    const float* W_ih     = (const float*)d_in[6];
    const float* b_ih     = (const float*)d_in[7];
    const float* W_hh     = (const float*)d_in[8];
    const float* b_hh     = (const float*)d_in[9];
    const float* conv1_w  = (const float*)d_in[10];
    const float* conv1_b  = (const float*)d_in[11];
    const float* conv2_w  = (const float*)d_in[12];
    const float* conv2_b  = (const float*)d_in[13];
    const float* convc1_w = (const float*)d_in[14];
    const float* convc1_b = (const float*)d_in[15];
    const float* convc2_w = (const float*)d_in[16];
    const float* convc2_b = (const float*)d_in[17];
    const float* mlp_y_w  = (const float*)d_in[18];
    const float* mlp_y_b  = (const float*)d_in[19];
    const float* mlp_z_w  = (const float*)d_in[20];
    const float* mlp_z_b  = (const float*)d_in[21];

    float* p_h0   = (float*)getsym(d_h0);
    float* p_h1   = (float*)getsym(d_h1);
    float* p_Amat = (float*)getsym(d_Amat);
    float* p_amsg = (float*)getsym(d_amsg);
    float* p_gi   = (float*)getsym(d_gi);
    float* p_gh   = (float*)getsym(d_gh);
    float* p_Wst  = (float*)getsym(d_Wstack);
    float* p_WihT = (float*)getsym(d_WihT);
    float* p_WhhT = (float*)getsym(d_WhhT);
    float* p_nb   = (float*)getsym(d_nbias);
    int*   p_deg4 = (int*)  getsym(d_deg4);
    float* p_cT   = (float*)getsym(d_cT);
    float* p_w1y  = (float*)getsym(d_w1y);
    float* p_w1z  = (float*)getsym(d_w1z);
    float* p_y1   = (float*)getsym(d_y1);
    float* p_z1   = (float*)getsym(d_z1);
    float* p_yp1  = (float*)getsym(d_yp1);
    float* p_zp1  = (float*)getsym(d_zp1);
    float* p_y2   = (float*)getsym(d_y2);
    float* p_z2   = (float*)getsym(d_z2);
    float* p_yp2  = (float*)getsym(d_yp2);
    float* p_zp2  = (float*)getsym(d_zp2);
    float* p_ly   = (float*)getsym(d_ly);
    float* p_lz   = (float*)getsym(d_lz);

    const int T = 256;

    // ---- first 4 launches: keep gh GEMM near profiler capture slot ----
    init_h_k<<<(NTOT * ODIM + T - 1) / T, T>>>(features);                    // 0
    pack_T_k<<<(ODIM * H3 + T - 1) / T, T>>>(W_hh, p_WhhT);                  // 1
    pack_T_k<<<(ODIM * H3 + T - 1) / T, T>>>(W_ih, p_WihT);                  // 2
    run_gemm(p_h0, p_WhhT, p_gh, b_hh, NTOT, H3, ODIM, ODIM, H3, H3, 1, 1, 0); // 3 (step-0 gh)

    // ---- rest of setup ----
    zero_int_k<<<(NTOT * 4 + T - 1) / T, T>>>(p_deg4, NTOT * 4);
    hist_k<<<(EDGES + T - 1) / T, T>>>(edst, etyp);
    scan_k<<<1, 1024>>>();
    chunk_hist_k<<<dim3(NCHK, BATCH), 512>>>(edst);
    chunk_scan_k<<<(NTOT + T - 1) / T, T>>>();
    scatter_k<<<dim3(NCHK, BATCH), 512>>>(esrc, edst, etyp);
    pack_wstack_k<<<(4 * ODIM * ODIM + T - 1) / T, T>>>(etype_W);
    pack_conv_k<<<(3 * ODIM * ODIM + T - 1) / T, T>>>(conv1_w, p_w1y, ODIM);
    pack_conv_k<<<(3 * CDIM * CDIM + T - 1) / T, T>>>(convc1_w, p_w1z, CDIM);
    nodebias_k<<<(NTOT * ODIM + T - 1) / T, T>>>(etype_b);

    // ---- GGNN: 8 steps ----
    for (int s = 0; s < 8; s++) {
        const float* hin  = (s & 1) ? p_h1 : p_h0;
        float*       hout = (s & 1) ? p_h0 : p_h1;
        spmm_k<<<NTOT, 256>>>(hin);
        run_gemm(p_Amat, p_Wst, p_amsg, p_nb, NTOT, ODIM, 800, 800, ODIM, ODIM, 2, 1, 0);
        run_gemm(p_amsg, p_WihT, p_gi, b_ih, NTOT, H3, ODIM, ODIM, H3, H3, 1, 1, 0);
        if (s > 0)
            run_gemm(hin, p_WhhT, p_gh, b_hh, NTOT, H3, ODIM, ODIM, H3, H3, 1, 1, 0);
        gates_k<<<(NTOT * 50 + T - 1) / T, T>>>(hin, hout);
    }
    float* p_hf = p_h0;

    // ---- readout ----
    transpose_k<<<dim3((ODIM + 31) / 32, NTOT / 32), dim3(32, 8)>>>(p_hf, p_cT, NTOT, ODIM);
    transpose_k<<<dim3((IDIM + 31) / 32, NTOT / 32), dim3(32, 8)>>>(features, p_cT + (size_t)ODIM * NTOT, NTOT, IDIM);

    run_gemm(p_w1y, p_cT, p_y1, conv1_b, ODIM, NTOT, ODIM, ODIM, NTOT, NTOT, 3, 3, ODIM * ODIM);
    pool3_k<<<(ODIM * GP1 + T - 1) / T, T>>>(p_y1, p_yp1, ODIM);
    run_gemm(conv2_w, p_yp1, p_y2, conv2_b, ODIM, GP1, ODIM, ODIM, GP1, GP1, 3, 1, 0);
    pool2_k<<<(ODIM * GP2 + T - 1) / T, T>>>(p_y2, p_yp2, ODIM);

    run_gemm(p_w1z, p_cT, p_z1, convc1_b, CDIM, NTOT, CDIM, CDIM, NTOT, NTOT, 3, 3, CDIM * CDIM);
    pool3_k<<<(CDIM * GP1 + T - 1) / T, T>>>(p_z1, p_zp1, CDIM);
    run_gemm(convc2_w, p_zp1, p_z2, convc2_b, CDIM, GP1, CDIM, CDIM, GP1, GP1, 3, 1, 0);
    pool2_k<<<(CDIM * GP2 + T - 1) / T, T>>>(p_z2, p_zp2, CDIM);

    run_gemm(mlp_y_w, p_yp2, p_ly, nullptr, NCLS, GP2, ODIM, ODIM, GP2, GP2, 0, 1, 0);
    run_gemm(mlp_z_w, p_zp2, p_lz, nullptr, NCLS, GP2, CDIM, CDIM, GP2, GP2, 0, 1, 0);

    final_k<<<BATCH, 128>>>(mlp_y_b, mlp_z_b, (float*)d_out);
}